// round 12
// baseline (speedup 1.0000x reference)
#include <cuda_runtime.h>
#include <cuda_fp16.h>
#include <cstdint>

// ---------------- problem constants ----------------
#define BATCH    2
#define LSEQ     2048
#define DMODEL   2048
#define INTERD   4096
#define NHEADS   64
#define HDIM     64
#define NSTATE   128
#define KCONV    4
#define CSIZE    256
#define NCHUNK   (LSEQ / CSIZE)                 // 8
#define CONVDIM  (INTERD + 2 * NSTATE)          // 4352
#define PROJDIM  (INTERD + CONVDIM + NHEADS)    // 8512
#define BL       (BATCH * LSEQ)                 // 4096
#define EPSV     1e-5f

// ---------------- device scratch (static; no allocs allowed) ----------------
__device__ __half g_projh [(size_t)BL * PROJDIM];
__device__ __half g_xBCh  [(size_t)BL * CONVDIM];
__device__ float g_dtv    [(size_t)BL * NHEADS];
__device__ float g_Acum   [(size_t)BATCH * NHEADS * NCHUNK * CSIZE];
__device__ __half g_CBh   [(size_t)BATCH * NCHUNK * CSIZE * CSIZE];
__device__ __half g_statesh[(size_t)BATCH * NCHUNK * NHEADS * HDIM * NSTATE];
__device__ __half g_prevh [(size_t)BATCH * NCHUNK * NHEADS * HDIM * NSTATE];
__device__ float g_Y      [(size_t)BL * INTERD];
__device__ __half g_A2    [(size_t)BL * DMODEL];
__device__ __half g_Win2  [(size_t)PROJDIM * DMODEL];
__device__ __half g_Y2    [(size_t)BL * INTERD];
__device__ __half g_Wout2 [(size_t)DMODEL * INTERD];

// =====================================================================
// common mma helpers
// =====================================================================
__device__ __forceinline__ uint32_t smem_u32(const void* p) {
    return (uint32_t)__cvta_generic_to_shared(p);
}
#define SW128(o) ((o) ^ (((o) >> 3) & 0x70))
#define SW256(o) ((o) ^ (((o) >> 4) & 0x70))

__device__ __forceinline__ void cp_async16(uint32_t d, const void* g, int sz) {
    asm volatile("cp.async.cg.shared.global [%0], [%1], 16, %2;"
                 :: "r"(d), "l"(g), "r"(sz) : "memory");
}
#define CP_COMMIT() asm volatile("cp.async.commit_group;" ::: "memory")
#define CP_WAIT1()  asm volatile("cp.async.wait_group 1;" ::: "memory")

__device__ __forceinline__ void ldsm4(uint32_t& r0, uint32_t& r1, uint32_t& r2,
                                      uint32_t& r3, uint32_t a) {
    asm volatile("ldmatrix.sync.aligned.m8n8.x4.shared.b16 {%0,%1,%2,%3}, [%4];"
                 : "=r"(r0), "=r"(r1), "=r"(r2), "=r"(r3) : "r"(a));
}
__device__ __forceinline__ void ldsm4t(uint32_t& r0, uint32_t& r1, uint32_t& r2,
                                       uint32_t& r3, uint32_t a) {
    asm volatile("ldmatrix.sync.aligned.m8n8.x4.trans.shared.b16 {%0,%1,%2,%3}, [%4];"
                 : "=r"(r0), "=r"(r1), "=r"(r2), "=r"(r3) : "r"(a));
}
__device__ __forceinline__ void mma16816(float* c, const uint32_t* a, const uint32_t* b) {
    asm volatile(
        "mma.sync.aligned.m16n8k16.row.col.f32.f16.f16.f32 "
        "{%0,%1,%2,%3}, {%4,%5,%6,%7}, {%8,%9}, {%0,%1,%2,%3};"
        : "+f"(c[0]), "+f"(c[1]), "+f"(c[2]), "+f"(c[3])
        : "r"(a[0]), "r"(a[1]), "r"(a[2]), "r"(a[3]), "r"(b[0]), "r"(b[1]));
}

__device__ __forceinline__ uint4 pack8h(const float* v) {
    __half h[8];
#pragma unroll
    for (int e = 0; e < 8; ++e) h[e] = __float2half(v[e]);
    uint4 r;
    r.x = ((uint32_t)*(uint16_t*)&h[1] << 16) | *(uint16_t*)&h[0];
    r.y = ((uint32_t)*(uint16_t*)&h[3] << 16) | *(uint16_t*)&h[2];
    r.z = ((uint32_t)*(uint16_t*)&h[5] << 16) | *(uint16_t*)&h[4];
    r.w = ((uint32_t)*(uint16_t*)&h[7] << 16) | *(uint16_t*)&h[6];
    return r;
}
__device__ __forceinline__ uint4 mul8h(uint4 v, __half2 w) {
    __half2* p = (__half2*)&v;
    p[0] = __hmul2(p[0], w); p[1] = __hmul2(p[1], w);
    p[2] = __hmul2(p[2], w); p[3] = __hmul2(p[3], w);
    return v;
}

__device__ __forceinline__ void store2(float* p, float a, float b) {
    *(float2*)p = make_float2(a, b);
}
__device__ __forceinline__ void store2(__half* p, float a, float b) {
    __half2 h; h.x = __float2half(a); h.y = __float2half(b);
    *(__half2*)p = h;
}

// =====================================================================
// big fp16 GEMM: BM=BN=128, BK=64, 3 stages, 256 threads, 2 CTAs/SM
// =====================================================================
#define TSTAGE_B (128 * 128 * 2)             // 32768
#define TNSTG    3
#define TSMEM    (TNSTG * TSTAGE_B)          // 98304

template <typename TOUT>
__global__ void __launch_bounds__(256, 2) gemm_fp16_mma(
    const __half* __restrict__ A, const __half* __restrict__ Bm,
    TOUT* __restrict__ C, int M, int N, int K, int ldc)
{
    extern __shared__ __align__(1024) char smem[];
    const uint32_t sbase = smem_u32(smem);
    const int tid  = threadIdx.x;
    const int wid  = tid >> 5, lane = tid & 31;
    const int bm   = blockIdx.x * 128, bn = blockIdx.y * 128;
    const int wm   = (wid & 1) * 64;
    const int wn   = (wid >> 1) * 32;
    const int KT   = K >> 6;

    float c[4][4][4];
#pragma unroll
    for (int mt = 0; mt < 4; ++mt)
#pragma unroll
        for (int nt = 0; nt < 4; ++nt)
#pragma unroll
            for (int q = 0; q < 4; ++q) c[mt][nt][q] = 0.f;

#define LOAD_STAGE(kt, s) do {                                               \
    uint32_t st_ = sbase + (s) * TSTAGE_B;                                   \
    _Pragma("unroll")                                                        \
    for (int i_ = 0; i_ < 4; ++i_) {                                         \
        int u_ = tid + i_ * 256;                                             \
        int r_ = u_ >> 3, lu_ = u_ & 7;                                      \
        uint32_t d_ = st_ + SW128((uint32_t)(r_ * 128 + lu_ * 16));          \
        const void* g_ = (const char*)A +                                    \
            (((size_t)(bm + r_) * K + (size_t)(kt) * 64 + lu_ * 8) << 1);    \
        cp_async16(d_, g_, 16);                                              \
    }                                                                        \
    _Pragma("unroll")                                                        \
    for (int i_ = 0; i_ < 4; ++i_) {                                         \
        int u_ = tid + i_ * 256;                                             \
        int r_ = u_ >> 3, lu_ = u_ & 7;                                      \
        int gn_ = bn + r_;                                                   \
        uint32_t d_ = st_ + 16384 + SW128((uint32_t)(r_ * 128 + lu_ * 16));  \
        const void* g_ = (const char*)Bm +                                   \
            (((size_t)gn_ * K + (size_t)(kt) * 64 + lu_ * 8) << 1);          \
        cp_async16(d_, g_, gn_ < N ? 16 : 0);                                \
    }                                                                        \
} while (0)

    LOAD_STAGE(0, 0); CP_COMMIT();
    LOAD_STAGE(1, 1); CP_COMMIT();

    const int a_row = (lane & 15);
    const int a_ku  = (lane >> 4) * 16;
    const int b_row = ((lane >> 4) & 1) * 8 + (lane & 7);
    const int b_ku  = ((lane >> 3) & 1) * 16;

    for (int kt = 0; kt < KT; ++kt) {
        const int s = kt % 3;
        CP_WAIT1();
        __syncthreads();
        if (kt + 2 < KT) LOAD_STAGE(kt + 2, (kt + 2) % 3);
        CP_COMMIT();

        const uint32_t stA = sbase + s * TSTAGE_B;
        const uint32_t stB = stA + 16384;
#pragma unroll
        for (int ks = 0; ks < 4; ++ks) {
            uint32_t a[4][4], b[4][2];
#pragma unroll
            for (int mt = 0; mt < 4; ++mt) {
                uint32_t off = (uint32_t)((wm + mt * 16 + a_row) * 128 + ks * 32 + a_ku);
                ldsm4(a[mt][0], a[mt][1], a[mt][2], a[mt][3], stA + SW128(off));
            }
#pragma unroll
            for (int pr = 0; pr < 2; ++pr) {
                uint32_t off = (uint32_t)((wn + pr * 16 + b_row) * 128 + ks * 32 + b_ku);
                uint32_t r0, r1, r2, r3;
                ldsm4(r0, r1, r2, r3, stB + SW128(off));
                b[pr * 2][0] = r0; b[pr * 2][1] = r1;
                b[pr * 2 + 1][0] = r2; b[pr * 2 + 1][1] = r3;
            }
#pragma unroll
            for (int mt = 0; mt < 4; ++mt)
#pragma unroll
                for (int nt = 0; nt < 4; ++nt)
                    mma16816(c[mt][nt], a[mt], b[nt]);
        }
    }

#pragma unroll
    for (int mt = 0; mt < 4; ++mt) {
        int r0 = bm + wm + mt * 16 + (lane >> 2);
#pragma unroll
        for (int nt = 0; nt < 4; ++nt) {
            int col = bn + wn + nt * 8 + (lane & 3) * 2;
            if (col < N) {
                store2(&C[(size_t)r0 * ldc + col], c[mt][nt][0], c[mt][nt][1]);
                store2(&C[(size_t)(r0 + 8) * ldc + col], c[mt][nt][2], c[mt][nt][3]);
            }
        }
    }
}

// ---------------- fused fp32 -> fp16 convert of hs, W_in, W_out ----------------
#define CVT_T1 ((long long)BL * DMODEL / 4)
#define CVT_T2 ((long long)PROJDIM * DMODEL / 4)
#define CVT_T3 ((long long)DMODEL * INTERD / 4)
__global__ void cvt_all_kernel(const float* __restrict__ hs,
                               const float* __restrict__ W_in,
                               const float* __restrict__ W_out,
                               __half* __restrict__ A2,
                               __half* __restrict__ Win2,
                               __half* __restrict__ Wout2)
{
    long long t = (long long)blockIdx.x * blockDim.x + threadIdx.x;
    const float* src; __half* dst; long long o;
    if (t < CVT_T1) { src = hs; dst = A2; o = t; }
    else if (t < CVT_T1 + CVT_T2) { src = W_in; dst = Win2; o = t - CVT_T1; }
    else if (t < CVT_T1 + CVT_T2 + CVT_T3) { src = W_out; dst = Wout2; o = t - CVT_T1 - CVT_T2; }
    else return;
    float4 a = *(const float4*)(src + o * 4);
    float v[4] = {a.x, a.y, a.z, a.w};
    __half h[4];
#pragma unroll
    for (int e = 0; e < 4; ++e) h[e] = __float2half(v[e]);
    uint2 r;
    r.x = ((uint32_t)*(uint16_t*)&h[1] << 16) | *(uint16_t*)&h[0];
    r.y = ((uint32_t)*(uint16_t*)&h[3] << 16) | *(uint16_t*)&h[2];
    *(uint2*)(dst + o * 4) = r;
}

// ---------------- depthwise causal conv (K=4) + bias + silu, 8 ch/thread ----------------
__global__ void conv_silu_kernel(const __half* __restrict__ projh,
                                 const float* __restrict__ cw,
                                 const float* __restrict__ cb,
                                 __half* __restrict__ xBCh)
{
    int idx = blockIdx.x * blockDim.x + threadIdx.x;   // one group of 8 channels
    if (idx >= BL * (CONVDIM / 8)) return;
    int g  = idx % (CONVDIM / 8);
    int bl = idx / (CONVDIM / 8);
    int ch = g * 8;
    int l  = bl % LSEQ;
    float acc[8];
#pragma unroll
    for (int e = 0; e < 8; ++e) acc[e] = cb[ch + e];
    // weights: 8 channels x 4 taps
    float w[8][4];
#pragma unroll
    for (int e = 0; e < 8; ++e) {
        float4 wv = *(const float4*)&cw[(ch + e) * 4];
        w[e][0] = wv.x; w[e][1] = wv.y; w[e][2] = wv.z; w[e][3] = wv.w;
    }
    const __half* base = projh + (size_t)bl * PROJDIM + INTERD + ch;
    int kmin = (l >= 3) ? 0 : (3 - l);
#pragma unroll
    for (int k = 0; k < 4; ++k) {
        if (k >= kmin) {
            uint4 v = *(const uint4*)(base + (k - 3) * PROJDIM);
            __half2* h2 = (__half2*)&v;
#pragma unroll
            for (int e2 = 0; e2 < 4; ++e2) {
                float2 f = __half22float2(h2[e2]);
                acc[e2 * 2]     += w[e2 * 2][k] * f.x;
                acc[e2 * 2 + 1] += w[e2 * 2 + 1][k] * f.y;
            }
        }
    }
    float o[8];
#pragma unroll
    for (int e = 0; e < 8; ++e) o[e] = acc[e] / (1.f + __expf(-acc[e]));
    *(uint4*)(xBCh + (size_t)bl * CONVDIM + ch) = pack8h(o);
}

// ---------------- softplus(dt+bias), per-chunk inclusive cumsum ----------------
__global__ void dt_acum_kernel(const __half* __restrict__ projh,
                               const float* __restrict__ dt_bias,
                               const float* __restrict__ A_log,
                               float* __restrict__ dtv,
                               float* __restrict__ Acum)
{
    int cc = blockIdx.x, h = blockIdx.y, b = blockIdx.z;
    int i  = threadIdx.x;
    int l  = cc * CSIZE + i;
    float d  = __half2float(projh[(size_t)(b * LSEQ + l) * PROJDIM + INTERD + CONVDIM + h])
             + dt_bias[h];
    float sp = (d > 20.f) ? d : log1pf(expf(d));
    dtv[(size_t)(b * LSEQ + l) * NHEADS + h] = sp;
    float dA = sp * (-expf(A_log[h]));
    __shared__ float sbuf[CSIZE];
    sbuf[i] = dA;
    __syncthreads();
    for (int off = 1; off < CSIZE; off <<= 1) {
        float v = sbuf[i];
        if (i >= off) v += sbuf[i - off];
        __syncthreads();
        sbuf[i] = v;
        __syncthreads();
    }
    Acum[(((size_t)b * NHEADS + h) * NCHUNK + cc) * CSIZE + i] = sbuf[i];
}

// =====================================================================
// CB via fp16 mma -> fp16 output
// =====================================================================
#define CB_SMEM (2 * 128 * 256)   // 65536 B
__global__ void __launch_bounds__(256) cb_mma(
    const __half* __restrict__ xBCh, __half* __restrict__ CBh)
{
    extern __shared__ __align__(1024) char sm[];
    __half* Cs = (__half*)sm;
    __half* Bs = (__half*)(sm + 32768);
    const uint32_t sC = smem_u32(Cs), sB = smem_u32(Bs);

    const int bj = blockIdx.x * 128, bi = blockIdx.y * 128;
    const int bc = blockIdx.z;
    const int b = bc / NCHUNK, cc = bc % NCHUNK;
    const int l0 = b * LSEQ + cc * CSIZE;
    const int tid = threadIdx.x, wid = tid >> 5, lane = tid & 31;
    const int wm = (wid & 1) * 64;
    const int wn = (wid >> 1) * 32;

#pragma unroll
    for (int it = 0; it < 8; ++it) {
        int u = tid + it * 256;
        int r = u >> 4, cu = u & 15;
        uint4 vc = *(const uint4*)&xBCh[(size_t)(l0 + bi + r) * CONVDIM + INTERD + NSTATE + cu * 8];
        uint4 vb = *(const uint4*)&xBCh[(size_t)(l0 + bj + r) * CONVDIM + INTERD + cu * 8];
        *(uint4*)((char*)Cs + SW256((uint32_t)(r * 256 + cu * 16))) = vc;
        *(uint4*)((char*)Bs + SW256((uint32_t)(r * 256 + cu * 16))) = vb;
    }
    __syncthreads();

    float c[4][4][4];
#pragma unroll
    for (int mt = 0; mt < 4; ++mt)
#pragma unroll
        for (int nt = 0; nt < 4; ++nt)
#pragma unroll
            for (int q = 0; q < 4; ++q) c[mt][nt][q] = 0.f;

    const int a_row = (lane & 15);
    const int a_ku  = (lane >> 4) * 16;
    const int b_row = ((lane >> 4) & 1) * 8 + (lane & 7);
    const int b_ku  = ((lane >> 3) & 1) * 16;

#pragma unroll
    for (int ks = 0; ks < 8; ++ks) {
        uint32_t a[4][4], bf[4][2];
#pragma unroll
        for (int mt = 0; mt < 4; ++mt) {
            uint32_t off = (uint32_t)((wm + mt * 16 + a_row) * 256 + ks * 32 + a_ku);
            ldsm4(a[mt][0], a[mt][1], a[mt][2], a[mt][3], sC + SW256(off));
        }
#pragma unroll
        for (int pr = 0; pr < 2; ++pr) {
            uint32_t off = (uint32_t)((wn + pr * 16 + b_row) * 256 + ks * 32 + b_ku);
            uint32_t r0, r1, r2, r3;
            ldsm4(r0, r1, r2, r3, sB + SW256(off));
            bf[pr * 2][0] = r0; bf[pr * 2][1] = r1;
            bf[pr * 2 + 1][0] = r2; bf[pr * 2 + 1][1] = r3;
        }
#pragma unroll
        for (int mt = 0; mt < 4; ++mt)
#pragma unroll
            for (int nt = 0; nt < 4; ++nt)
                mma16816(c[mt][nt], a[mt], bf[nt]);
    }

    __half* cbo = CBh + (size_t)bc * CSIZE * CSIZE;
#pragma unroll
    for (int mt = 0; mt < 4; ++mt) {
        int gi = bi + wm + mt * 16 + (lane >> 2);
#pragma unroll
        for (int nt = 0; nt < 4; ++nt) {
            int gj = bj + wn + nt * 8 + (lane & 3) * 2;
            store2(&cbo[(size_t)gi * CSIZE + gj], c[mt][nt][0], c[mt][nt][1]);
            store2(&cbo[(size_t)(gi + 8) * CSIZE + gj], c[mt][nt][2], c[mt][nt][3]);
        }
    }
}

// =====================================================================
// states via mma -> fp16 output
// =====================================================================
#define SSM_SMEM (16384 + 32768 + 512)
__global__ void __launch_bounds__(128) states_mma(
    const __half* __restrict__ xBCh, const float* __restrict__ dtv,
    const float* __restrict__ Acum, __half* __restrict__ statesh)
{
    extern __shared__ __align__(1024) char sm[];
    __half* Xw = (__half*)sm;
    __half* Bs = (__half*)(sm + 16384);
    float*  wv = (float*)(sm + 49152);
    const uint32_t sX = smem_u32(Xw), sB = smem_u32(Bs);

    const int cc = blockIdx.x, h = blockIdx.y, b = blockIdx.z;
    const int tid = threadIdx.x, wid = tid >> 5, lane = tid & 31;
    const float* Ab = Acum + (((size_t)b * NHEADS + h) * NCHUNK + cc) * CSIZE;
    const float AcLast = Ab[CSIZE - 1];
    const int l0 = b * LSEQ + cc * CSIZE;

    float c[4][4][4];
#pragma unroll
    for (int mt = 0; mt < 4; ++mt)
#pragma unroll
        for (int nt = 0; nt < 4; ++nt)
#pragma unroll
            for (int q = 0; q < 4; ++q) c[mt][nt][q] = 0.f;

    for (int jt = 0; jt < CSIZE; jt += 128) {
        wv[tid] = __expf(AcLast - Ab[jt + tid]) * dtv[(size_t)(l0 + jt + tid) * NHEADS + h];
        __syncthreads();
#pragma unroll
        for (int it = 0; it < 8; ++it) {
            int u = tid + it * 128;
            int j = u >> 3, cu = u & 7;
            uint4 v = *(const uint4*)&xBCh[(size_t)(l0 + jt + j) * CONVDIM + h * HDIM + cu * 8];
            __half2 w2 = __float2half2_rn(wv[j]);
            *(uint4*)((char*)Xw + SW128((uint32_t)(j * 128 + cu * 16))) = mul8h(v, w2);
        }
#pragma unroll
        for (int it = 0; it < 16; ++it) {
            int u = tid + it * 128;
            int j = u >> 4, cu = u & 15;
            uint4 v = *(const uint4*)&xBCh[(size_t)(l0 + jt + j) * CONVDIM + INTERD + cu * 8];
            *(uint4*)((char*)Bs + SW256((uint32_t)(j * 256 + cu * 16))) = v;
        }
        __syncthreads();
#pragma unroll
        for (int ks = 0; ks < 8; ++ks) {
            uint32_t a[4][4], bf[4][2];
#pragma unroll
            for (int mt = 0; mt < 4; ++mt) {
                int row = ks * 16 + ((lane >> 4) & 1) * 8 + (lane & 7);
                int col = mt * 16 + ((lane >> 3) & 1) * 8;
                ldsm4t(a[mt][0], a[mt][1], a[mt][2], a[mt][3],
                       sX + SW128((uint32_t)(row * 128 + col * 2)));
            }
#pragma unroll
            for (int nt2 = 0; nt2 < 2; ++nt2) {
                int row = ks * 16 + ((lane >> 3) & 1) * 8 + (lane & 7);
                int col = wid * 32 + nt2 * 16 + (lane >> 4) * 8;
                uint32_t r0, r1, r2, r3;
                ldsm4t(r0, r1, r2, r3, sB + SW256((uint32_t)(row * 256 + col * 2)));
                bf[nt2 * 2][0] = r0; bf[nt2 * 2][1] = r1;
                bf[nt2 * 2 + 1][0] = r2; bf[nt2 * 2 + 1][1] = r3;
            }
#pragma unroll
            for (int mt = 0; mt < 4; ++mt)
#pragma unroll
                for (int nt = 0; nt < 4; ++nt)
                    mma16816(c[mt][nt], a[mt], bf[nt]);
        }
        __syncthreads();
    }
    __half* so = statesh + (((size_t)b * NCHUNK + cc) * NHEADS + h) * (HDIM * NSTATE);
#pragma unroll
    for (int mt = 0; mt < 4; ++mt) {
        int p0 = mt * 16 + (lane >> 2);
#pragma unroll
        for (int nt = 0; nt < 4; ++nt) {
            int n = wid * 32 + nt * 8 + (lane & 3) * 2;
            store2(&so[p0 * NSTATE + n], c[mt][nt][0], c[mt][nt][1]);
            store2(&so[(p0 + 8) * NSTATE + n], c[mt][nt][2], c[mt][nt][3]);
        }
    }
}

// ---------------- inter-chunk recurrence (fp16 states -> fp16 prev) ----------------
__global__ void scan_kernel(const __half* __restrict__ statesh,
                            const float* __restrict__ Acum,
                            __half* __restrict__ prevh)
{
    int h = blockIdx.x, b = blockIdx.y, tid = threadIdx.x;
    float carry[32];
#pragma unroll
    for (int t = 0; t < 32; ++t) carry[t] = 0.f;
    for (int cc = 0; cc < NCHUNK; ++cc) {
        float cd = expf(Acum[(((size_t)b * NHEADS + h) * NCHUNK + cc) * CSIZE + CSIZE - 1]);
        size_t base = (((size_t)b * NCHUNK + cc) * NHEADS + h) * (HDIM * NSTATE);
#pragma unroll
        for (int t = 0; t < 32; ++t) {
            size_t idx = base + tid + t * 256;
            prevh[idx] = __float2half(carry[t]);
            carry[t]   = cd * carry[t] + __half2float(statesh[idx]);
        }
    }
}

// =====================================================================
// Y via mma: Y[i,p] = M @ X + Ce @ prev^T + D*x
// =====================================================================
__global__ void __launch_bounds__(256) y_mma(
    const __half* __restrict__ xBCh, const float* __restrict__ dtv,
    const float* __restrict__ Acum, const __half* __restrict__ CBh,
    const __half* __restrict__ prevh, const float* __restrict__ Dp,
    float* __restrict__ Y)
{
    __shared__ float Ac[CSIZE], dts[CSIZE], rowf[CSIZE], eA[CSIZE], colf[64];
    __shared__ __align__(1024) __half Ms[CSIZE * 64];
    __shared__ __align__(1024) __half Xs[64 * 64];
    const uint32_t sM = smem_u32(Ms), sXs = smem_u32(Xs);

    const int cc = blockIdx.x, h = blockIdx.y, b = blockIdx.z;
    const int tid = threadIdx.x, wid = tid >> 5, lane = tid & 31;
    const int wm = (wid & 3) * 64;
    const int wn = (wid >> 2) * 32;
    const int l0 = b * LSEQ + cc * CSIZE;

    Ac[tid]  = Acum[(((size_t)b * NHEADS + h) * NCHUNK + cc) * CSIZE + tid];
    dts[tid] = dtv[(size_t)(l0 + tid) * NHEADS + h];
    __syncthreads();
    eA[tid] = __expf(Ac[tid]);

    const __half* CBb = CBh + ((size_t)b * NCHUNK + cc) * CSIZE * CSIZE;

    float c[4][4][4];
#pragma unroll
    for (int mt = 0; mt < 4; ++mt)
#pragma unroll
        for (int nt = 0; nt < 4; ++nt)
#pragma unroll
            for (int q = 0; q < 4; ++q) c[mt][nt][q] = 0.f;

    for (int jt = 0; jt < CSIZE; jt += 64) {
        float A_ref = Ac[jt + 63];
        if (tid < 64) colf[tid] = __expf(A_ref - Ac[jt + tid]) * dts[jt + tid];
        rowf[tid] = __expf(Ac[tid] - A_ref);
        __syncthreads();
#pragma unroll
        for (int it = 0; it < 8; ++it) {
            int u = tid + it * 256;
            int i = u >> 3, cu = u & 7;
            float v[8];
            if (i < jt) {
#pragma unroll
                for (int e = 0; e < 8; ++e) v[e] = 0.f;
            } else {
                uint4 cbv = *(const uint4*)&CBb[(size_t)i * CSIZE + jt + cu * 8];
                __half2* ch2 = (__half2*)&cbv;
                float cf[8];
#pragma unroll
                for (int e2 = 0; e2 < 4; ++e2) {
                    float2 f = __half22float2(ch2[e2]);
                    cf[e2 * 2] = f.x; cf[e2 * 2 + 1] = f.y;
                }
                if (i >= jt + 64) {
                    float rf = rowf[i];
#pragma unroll
                    for (int e = 0; e < 8; ++e) v[e] = cf[e] * rf * colf[cu * 8 + e];
                } else {
#pragma unroll
                    for (int e = 0; e < 8; ++e) {
                        int j = jt + cu * 8 + e;
                        v[e] = (j <= i) ? cf[e] * __expf(Ac[i] - Ac[j]) * dts[j] : 0.f;
                    }
                }
            }
            *(uint4*)((char*)Ms + SW128((uint32_t)(i * 128 + cu * 16))) = pack8h(v);
        }
#pragma unroll
        for (int it = 0; it < 2; ++it) {
            int u = tid + it * 256;
            int j = u >> 3, cu = u & 7;
            uint4 v = *(const uint4*)&xBCh[(size_t)(l0 + jt + j) * CONVDIM + h * HDIM + cu * 8];
            *(uint4*)((char*)Xs + SW128((uint32_t)(j * 128 + cu * 16))) = v;
        }
        __syncthreads();
#pragma unroll
        for (int ks = 0; ks < 4; ++ks) {
            uint32_t a[4][4], bf[4][2];
#pragma unroll
            for (int mt = 0; mt < 4; ++mt) {
                int row = wm + mt * 16 + (lane & 15);
                int kb  = ks * 32 + (lane >> 4) * 16;
                ldsm4(a[mt][0], a[mt][1], a[mt][2], a[mt][3],
                      sM + SW128((uint32_t)(row * 128 + kb)));
            }
#pragma unroll
            for (int nt2 = 0; nt2 < 2; ++nt2) {
                int row = ks * 16 + ((lane >> 3) & 1) * 8 + (lane & 7);
                int col = wn + nt2 * 16 + (lane >> 4) * 8;
                uint32_t r0, r1, r2, r3;
                ldsm4t(r0, r1, r2, r3, sXs + SW128((uint32_t)(row * 128 + col * 2)));
                bf[nt2 * 2][0] = r0; bf[nt2 * 2][1] = r1;
                bf[nt2 * 2 + 1][0] = r2; bf[nt2 * 2 + 1][1] = r3;
            }
#pragma unroll
            for (int mt = 0; mt < 4; ++mt)
#pragma unroll
                for (int nt = 0; nt < 4; ++nt)
                    mma16816(c[mt][nt], a[mt], bf[nt]);
        }
        __syncthreads();
    }

    const __half* pvb = prevh + (((size_t)b * NCHUNK + cc) * NHEADS + h) * (HDIM * NSTATE);
    for (int nt0 = 0; nt0 < NSTATE; nt0 += 64) {
#pragma unroll
        for (int it = 0; it < 8; ++it) {
            int u = tid + it * 256;
            int i = u >> 3, cu = u & 7;
            uint4 v = *(const uint4*)&xBCh[(size_t)(l0 + i) * CONVDIM + INTERD + NSTATE + nt0 + cu * 8];
            __half2 ea2 = __float2half2_rn(eA[i]);
            *(uint4*)((char*)Ms + SW128((uint32_t)(i * 128 + cu * 16))) = mul8h(v, ea2);
        }
#pragma unroll
        for (int it = 0; it < 2; ++it) {
            int u = tid + it * 256;
            int p = u >> 3, cu = u & 7;
            uint4 v = *(const uint4*)(pvb + (size_t)p * NSTATE + nt0 + cu * 8);
            *(uint4*)((char*)Xs + SW128((uint32_t)(p * 128 + cu * 16))) = v;
        }
        __syncthreads();
#pragma unroll
        for (int ks = 0; ks < 4; ++ks) {
            uint32_t a[4][4], bf[4][2];
#pragma unroll
            for (int mt = 0; mt < 4; ++mt) {
                int row = wm + mt * 16 + (lane & 15);
                int kb  = ks * 32 + (lane >> 4) * 16;
                ldsm4(a[mt][0], a[mt][1], a[mt][2], a[mt][3],
                      sM + SW128((uint32_t)(row * 128 + kb)));
            }
#pragma unroll
            for (int nt2 = 0; nt2 < 2; ++nt2) {
                int prow = wn + nt2 * 16 + ((lane >> 4) & 1) * 8 + (lane & 7);
                int kb   = ks * 32 + ((lane >> 3) & 1) * 16;
                uint32_t r0, r1, r2, r3;
                ldsm4(r0, r1, r2, r3, sXs + SW128((uint32_t)(prow * 128 + kb)));
                bf[nt2 * 2][0] = r0; bf[nt2 * 2][1] = r1;
                bf[nt2 * 2 + 1][0] = r2; bf[nt2 * 2 + 1][1] = r3;
            }
#pragma unroll
            for (int mt = 0; mt < 4; ++mt)
#pragma unroll
                for (int nt = 0; nt < 4; ++nt)
                    mma16816(c[mt][nt], a[mt], bf[nt]);
        }
        __syncthreads();
    }

    float Dh = Dp[h];
#pragma unroll
    for (int mt = 0; mt < 4; ++mt) {
        int i0 = wm + mt * 16 + (lane >> 2);
#pragma unroll
        for (int nt = 0; nt < 4; ++nt) {
            int p = wn + nt * 8 + (lane & 3) * 2;
#pragma unroll
            for (int half = 0; half < 2; ++half) {
                int i = i0 + half * 8;
                __half2 xh = *(const __half2*)&xBCh[(size_t)(l0 + i) * CONVDIM + h * HDIM + p];
                float2 xv = __half22float2(xh);
                float2 ov;
                ov.x = c[mt][nt][half * 2 + 0] + Dh * xv.x;
                ov.y = c[mt][nt][half * 2 + 1] + Dh * xv.y;
                *(float2*)&Y[(size_t)(l0 + i) * INTERD + h * HDIM + p] = ov;
            }
        }
    }
}

// ---------------- gate (silu, fp16 in) + RMSNorm -> fp16 Y2 ----------------
__global__ void gate_rms_kernel(const __half* __restrict__ projh,
                                const float* __restrict__ norm_w,
                                const float* __restrict__ Y,
                                __half* __restrict__ Y2)
{
    int row = blockIdx.x, tid = threadIdx.x;
    const __half* gr = projh + (size_t)row * PROJDIM;
    const float* yr = Y + (size_t)row * INTERD;
    float yv[16];
    float ss = 0.f;
#pragma unroll
    for (int t = 0; t < 16; ++t) {
        int e = tid + t * 256;
        float g = __half2float(gr[e]);
        float v = yr[e] * (g / (1.f + __expf(-g)));
        yv[t] = v;
        ss += v * v;
    }
    __shared__ float red[8];
#pragma unroll
    for (int o = 16; o > 0; o >>= 1) ss += __shfl_xor_sync(0xffffffff, ss, o);
    if ((tid & 31) == 0) red[tid >> 5] = ss;
    __syncthreads();
    float tot = 0.f;
#pragma unroll
    for (int w = 0; w < 8; ++w) tot += red[w];
    float scale = rsqrtf(tot / (float)INTERD + EPSV);
    __half* y2r = Y2 + (size_t)row * INTERD;
#pragma unroll
    for (int t = 0; t < 16; ++t) {
        int e = tid + t * 256;
        y2r[e] = __float2half(yv[t] * scale * norm_w[e]);
    }
}

// ---------------- launch ----------------
extern "C" void kernel_launch(void* const* d_in, const int* in_sizes, int n_in,
                              void* d_out, int out_size)
{
    const float* hs      = (const float*)d_in[0];
    const float* W_in    = (const float*)d_in[1];
    const float* conv_w  = (const float*)d_in[2];
    const float* conv_b  = (const float*)d_in[3];
    const float* dt_bias = (const float*)d_in[4];
    const float* A_log   = (const float*)d_in[5];
    const float* Dp      = (const float*)d_in[6];
    const float* norm_w  = (const float*)d_in[7];
    const float* W_out   = (const float*)d_in[8];
    float* out = (float*)d_out;

    float *dtv, *Acum, *Y;
    __half *projh, *xBCh, *CBh, *statesh, *prevh, *A2, *Win2, *Y2, *Wout2;
    cudaGetSymbolAddress((void**)&projh,   g_projh);
    cudaGetSymbolAddress((void**)&xBCh,    g_xBCh);
    cudaGetSymbolAddress((void**)&dtv,     g_dtv);
    cudaGetSymbolAddress((void**)&Acum,    g_Acum);
    cudaGetSymbolAddress((void**)&CBh,     g_CBh);
    cudaGetSymbolAddress((void**)&statesh, g_statesh);
    cudaGetSymbolAddress((void**)&prevh,   g_prevh);
    cudaGetSymbolAddress((void**)&Y,       g_Y);
    cudaGetSymbolAddress((void**)&A2,      g_A2);
    cudaGetSymbolAddress((void**)&Win2,    g_Win2);
    cudaGetSymbolAddress((void**)&Y2,      g_Y2);
    cudaGetSymbolAddress((void**)&Wout2,   g_Wout2);

    cudaFuncSetAttribute(gemm_fp16_mma<__half>,
                         cudaFuncAttributeMaxDynamicSharedMemorySize, TSMEM);
    cudaFuncSetAttribute(gemm_fp16_mma<float>,
                         cudaFuncAttributeMaxDynamicSharedMemorySize, TSMEM);
    cudaFuncSetAttribute(states_mma,
                         cudaFuncAttributeMaxDynamicSharedMemorySize, SSM_SMEM);
    cudaFuncSetAttribute(cb_mma,
                         cudaFuncAttributeMaxDynamicSharedMemorySize, CB_SMEM);

    // side stream + events (created once; used in graph-captured fork/join)
    static cudaStream_t s1 = nullptr;
    static cudaEvent_t evCvt = nullptr, evGate = nullptr;
    if (!s1) {
        cudaStreamCreateWithFlags(&s1, cudaStreamNonBlocking);
        cudaEventCreateWithFlags(&evCvt, cudaEventDisableTiming);
        cudaEventCreateWithFlags(&evGate, cudaEventDisableTiming);
    }

    // 0) fused fp32 -> fp16 conversion (hs, W_in, W_out)
    {
        long long tot = CVT_T1 + CVT_T2 + CVT_T3;
        cvt_all_kernel<<<(unsigned)((tot + 255) / 256), 256>>>(
            hs, W_in, W_out, A2, Win2, Wout2);
    }
    cudaEventRecord(evCvt, 0);

    // 1a) proj[:, INTERD:] = hs @ W_in[INTERD:,:]^T  (xBC + dt columns, feeds SSM)
    gemm_fp16_mma<__half><<<dim3(BL / 128, (CONVDIM + NHEADS + 127) / 128), 256, TSMEM>>>(
        A2, Win2 + (size_t)INTERD * DMODEL, projh + INTERD,
        BL, CONVDIM + NHEADS, DMODEL, PROJDIM);

    // 1b) proj[:, :INTERD] = hs @ W_in[:INTERD,:]^T  (gate columns) on side stream,
    //     overlapped with the whole SSM chain; joined before gate_rms.
    cudaStreamWaitEvent(s1, evCvt, 0);
    gemm_fp16_mma<__half><<<dim3(BL / 128, INTERD / 128), 256, TSMEM, s1>>>(
        A2, Win2, projh, BL, INTERD, DMODEL, PROJDIM);
    cudaEventRecord(evGate, s1);

    // 2) conv + silu -> fp16 xBC (8 ch/thread)
    {
        int total8 = BL * (CONVDIM / 8);
        conv_silu_kernel<<<(total8 + 255) / 256, 256>>>(projh, conv_w, conv_b, xBCh);
    }

    // 3) softplus(dt) + cumsum
    dt_acum_kernel<<<dim3(NCHUNK, NHEADS, BATCH), CSIZE>>>(projh, dt_bias, A_log, dtv, Acum);

    // 4) CB = C . B^T via fp16 mma -> fp16
    cb_mma<<<dim3(2, 2, BATCH * NCHUNK), 256, CB_SMEM>>>(xBCh, CBh);

    // 5) states via mma -> fp16
    states_mma<<<dim3(NCHUNK, NHEADS, BATCH), 128, SSM_SMEM>>>(xBCh, dtv, Acum, statesh);

    // 6) scan -> fp16 prev
    scan_kernel<<<dim3(NHEADS, BATCH), 256>>>(statesh, Acum, prevh);

    // 7) Y via mma (Ydiag + Yoff + D*x)
    y_mma<<<dim3(NCHUNK, NHEADS, BATCH), 256>>>(xBCh, dtv, Acum, CBh, prevh, Dp, Y);

    // join: gate columns must be ready
    cudaStreamWaitEvent(0, evGate, 0);

    // 8) gate + RMSNorm -> fp16
    gate_rms_kernel<<<BL, 256>>>(projh, norm_w, Y, Y2);

    // 9) out = Y @ W_out^T (fp32 output)
    gemm_fp16_mma<float><<<dim3(BL / 128, DMODEL / 128), 256, TSMEM>>>(
        Y2, Wout2, out, BL, DMODEL, INTERD, DMODEL);
}

// round 13
// speedup vs baseline: 1.1012x; 1.1012x over previous
#include <cuda_runtime.h>
#include <cuda_fp16.h>
#include <cstdint>

// ---------------- problem constants ----------------
#define BATCH    2
#define LSEQ     2048
#define DMODEL   2048
#define INTERD   4096
#define NHEADS   64
#define HDIM     64
#define NSTATE   128
#define KCONV    4
#define CSIZE    256
#define NCHUNK   (LSEQ / CSIZE)                 // 8
#define CONVDIM  (INTERD + 2 * NSTATE)          // 4352
#define PROJDIM  (INTERD + CONVDIM + NHEADS)    // 8512
#define BL       (BATCH * LSEQ)                 // 4096
#define EPSV     1e-5f

// ---------------- device scratch (static; no allocs allowed) ----------------
__device__ __half g_projh [(size_t)BL * PROJDIM];
__device__ __half g_xBCh  [(size_t)BL * CONVDIM];
__device__ float g_dtv    [(size_t)BL * NHEADS];
__device__ float g_Acum   [(size_t)BATCH * NHEADS * NCHUNK * CSIZE];
__device__ __half g_CBh   [(size_t)BATCH * NCHUNK * CSIZE * CSIZE];
__device__ __half g_statesh[(size_t)BATCH * NCHUNK * NHEADS * HDIM * NSTATE];
__device__ __half g_prevh [(size_t)BATCH * NCHUNK * NHEADS * HDIM * NSTATE];
__device__ float g_Y      [(size_t)BL * INTERD];
__device__ __half g_A2    [(size_t)BL * DMODEL];
__device__ __half g_Win2  [(size_t)PROJDIM * DMODEL];
__device__ __half g_Y2    [(size_t)BL * INTERD];
__device__ __half g_Wout2 [(size_t)DMODEL * INTERD];

// =====================================================================
// common mma helpers
// =====================================================================
__device__ __forceinline__ uint32_t smem_u32(const void* p) {
    return (uint32_t)__cvta_generic_to_shared(p);
}
#define SW128(o) ((o) ^ (((o) >> 3) & 0x70))
#define SW256(o) ((o) ^ (((o) >> 4) & 0x70))

__device__ __forceinline__ void cp_async16(uint32_t d, const void* g, int sz) {
    asm volatile("cp.async.cg.shared.global [%0], [%1], 16, %2;"
                 :: "r"(d), "l"(g), "r"(sz) : "memory");
}
#define CP_COMMIT() asm volatile("cp.async.commit_group;" ::: "memory")
#define CP_WAIT1()  asm volatile("cp.async.wait_group 1;" ::: "memory")

__device__ __forceinline__ void ldsm4(uint32_t& r0, uint32_t& r1, uint32_t& r2,
                                      uint32_t& r3, uint32_t a) {
    asm volatile("ldmatrix.sync.aligned.m8n8.x4.shared.b16 {%0,%1,%2,%3}, [%4];"
                 : "=r"(r0), "=r"(r1), "=r"(r2), "=r"(r3) : "r"(a));
}
__device__ __forceinline__ void ldsm4t(uint32_t& r0, uint32_t& r1, uint32_t& r2,
                                       uint32_t& r3, uint32_t a) {
    asm volatile("ldmatrix.sync.aligned.m8n8.x4.trans.shared.b16 {%0,%1,%2,%3}, [%4];"
                 : "=r"(r0), "=r"(r1), "=r"(r2), "=r"(r3) : "r"(a));
}
__device__ __forceinline__ void mma16816(float* c, const uint32_t* a, const uint32_t* b) {
    asm volatile(
        "mma.sync.aligned.m16n8k16.row.col.f32.f16.f16.f32 "
        "{%0,%1,%2,%3}, {%4,%5,%6,%7}, {%8,%9}, {%0,%1,%2,%3};"
        : "+f"(c[0]), "+f"(c[1]), "+f"(c[2]), "+f"(c[3])
        : "r"(a[0]), "r"(a[1]), "r"(a[2]), "r"(a[3]), "r"(b[0]), "r"(b[1]));
}

__device__ __forceinline__ uint4 pack8h(const float* v) {
    __half h[8];
#pragma unroll
    for (int e = 0; e < 8; ++e) h[e] = __float2half(v[e]);
    uint4 r;
    r.x = ((uint32_t)*(uint16_t*)&h[1] << 16) | *(uint16_t*)&h[0];
    r.y = ((uint32_t)*(uint16_t*)&h[3] << 16) | *(uint16_t*)&h[2];
    r.z = ((uint32_t)*(uint16_t*)&h[5] << 16) | *(uint16_t*)&h[4];
    r.w = ((uint32_t)*(uint16_t*)&h[7] << 16) | *(uint16_t*)&h[6];
    return r;
}
__device__ __forceinline__ uint4 mul8h(uint4 v, __half2 w) {
    __half2* p = (__half2*)&v;
    p[0] = __hmul2(p[0], w); p[1] = __hmul2(p[1], w);
    p[2] = __hmul2(p[2], w); p[3] = __hmul2(p[3], w);
    return v;
}

__device__ __forceinline__ void store2(float* p, float a, float b) {
    *(float2*)p = make_float2(a, b);
}
__device__ __forceinline__ void store2(__half* p, float a, float b) {
    __half2 h; h.x = __float2half(a); h.y = __float2half(b);
    *(__half2*)p = h;
}

// =====================================================================
// big fp16 GEMM: BM=BN=128, BK=64, 3 stages, 256 threads, 2 CTAs/SM
// =====================================================================
#define TSTAGE_B (128 * 128 * 2)             // 32768
#define TNSTG    3
#define TSMEM    (TNSTG * TSTAGE_B)          // 98304

template <typename TOUT>
__global__ void __launch_bounds__(256, 2) gemm_fp16_mma(
    const __half* __restrict__ A, const __half* __restrict__ Bm,
    TOUT* __restrict__ C, int M, int N, int K, int ldc)
{
    extern __shared__ __align__(1024) char smem[];
    const uint32_t sbase = smem_u32(smem);
    const int tid  = threadIdx.x;
    const int wid  = tid >> 5, lane = tid & 31;
    const int bm   = blockIdx.x * 128, bn = blockIdx.y * 128;
    const int wm   = (wid & 1) * 64;
    const int wn   = (wid >> 1) * 32;
    const int KT   = K >> 6;

    float c[4][4][4];
#pragma unroll
    for (int mt = 0; mt < 4; ++mt)
#pragma unroll
        for (int nt = 0; nt < 4; ++nt)
#pragma unroll
            for (int q = 0; q < 4; ++q) c[mt][nt][q] = 0.f;

#define LOAD_STAGE(kt, s) do {                                               \
    uint32_t st_ = sbase + (s) * TSTAGE_B;                                   \
    _Pragma("unroll")                                                        \
    for (int i_ = 0; i_ < 4; ++i_) {                                         \
        int u_ = tid + i_ * 256;                                             \
        int r_ = u_ >> 3, lu_ = u_ & 7;                                      \
        uint32_t d_ = st_ + SW128((uint32_t)(r_ * 128 + lu_ * 16));          \
        const void* g_ = (const char*)A +                                    \
            (((size_t)(bm + r_) * K + (size_t)(kt) * 64 + lu_ * 8) << 1);    \
        cp_async16(d_, g_, 16);                                              \
    }                                                                        \
    _Pragma("unroll")                                                        \
    for (int i_ = 0; i_ < 4; ++i_) {                                         \
        int u_ = tid + i_ * 256;                                             \
        int r_ = u_ >> 3, lu_ = u_ & 7;                                      \
        int gn_ = bn + r_;                                                   \
        uint32_t d_ = st_ + 16384 + SW128((uint32_t)(r_ * 128 + lu_ * 16));  \
        const void* g_ = (const char*)Bm +                                   \
            (((size_t)gn_ * K + (size_t)(kt) * 64 + lu_ * 8) << 1);          \
        cp_async16(d_, g_, gn_ < N ? 16 : 0);                                \
    }                                                                        \
} while (0)

    LOAD_STAGE(0, 0); CP_COMMIT();
    LOAD_STAGE(1, 1); CP_COMMIT();

    const int a_row = (lane & 15);
    const int a_ku  = (lane >> 4) * 16;
    const int b_row = ((lane >> 4) & 1) * 8 + (lane & 7);
    const int b_ku  = ((lane >> 3) & 1) * 16;

    for (int kt = 0; kt < KT; ++kt) {
        const int s = kt % 3;
        CP_WAIT1();
        __syncthreads();
        if (kt + 2 < KT) LOAD_STAGE(kt + 2, (kt + 2) % 3);
        CP_COMMIT();

        const uint32_t stA = sbase + s * TSTAGE_B;
        const uint32_t stB = stA + 16384;
#pragma unroll
        for (int ks = 0; ks < 4; ++ks) {
            uint32_t a[4][4], b[4][2];
#pragma unroll
            for (int mt = 0; mt < 4; ++mt) {
                uint32_t off = (uint32_t)((wm + mt * 16 + a_row) * 128 + ks * 32 + a_ku);
                ldsm4(a[mt][0], a[mt][1], a[mt][2], a[mt][3], stA + SW128(off));
            }
#pragma unroll
            for (int pr = 0; pr < 2; ++pr) {
                uint32_t off = (uint32_t)((wn + pr * 16 + b_row) * 128 + ks * 32 + b_ku);
                uint32_t r0, r1, r2, r3;
                ldsm4(r0, r1, r2, r3, stB + SW128(off));
                b[pr * 2][0] = r0; b[pr * 2][1] = r1;
                b[pr * 2 + 1][0] = r2; b[pr * 2 + 1][1] = r3;
            }
#pragma unroll
            for (int mt = 0; mt < 4; ++mt)
#pragma unroll
                for (int nt = 0; nt < 4; ++nt)
                    mma16816(c[mt][nt], a[mt], b[nt]);
        }
    }

#pragma unroll
    for (int mt = 0; mt < 4; ++mt) {
        int r0 = bm + wm + mt * 16 + (lane >> 2);
#pragma unroll
        for (int nt = 0; nt < 4; ++nt) {
            int col = bn + wn + nt * 8 + (lane & 3) * 2;
            if (col < N) {
                store2(&C[(size_t)r0 * ldc + col], c[mt][nt][0], c[mt][nt][1]);
                store2(&C[(size_t)(r0 + 8) * ldc + col], c[mt][nt][2], c[mt][nt][3]);
            }
        }
    }
}

// ---------------- fused fp32 -> fp16 convert of hs, W_in, W_out ----------------
#define CVT_T1 ((long long)BL * DMODEL / 4)
#define CVT_T2 ((long long)PROJDIM * DMODEL / 4)
#define CVT_T3 ((long long)DMODEL * INTERD / 4)
__global__ void cvt_all_kernel(const float* __restrict__ hs,
                               const float* __restrict__ W_in,
                               const float* __restrict__ W_out,
                               __half* __restrict__ A2,
                               __half* __restrict__ Win2,
                               __half* __restrict__ Wout2)
{
    long long t = (long long)blockIdx.x * blockDim.x + threadIdx.x;
    const float* src; __half* dst; long long o;
    if (t < CVT_T1) { src = hs; dst = A2; o = t; }
    else if (t < CVT_T1 + CVT_T2) { src = W_in; dst = Win2; o = t - CVT_T1; }
    else if (t < CVT_T1 + CVT_T2 + CVT_T3) { src = W_out; dst = Wout2; o = t - CVT_T1 - CVT_T2; }
    else return;
    float4 a = *(const float4*)(src + o * 4);
    float v[4] = {a.x, a.y, a.z, a.w};
    __half h[4];
#pragma unroll
    for (int e = 0; e < 4; ++e) h[e] = __float2half(v[e]);
    uint2 r;
    r.x = ((uint32_t)*(uint16_t*)&h[1] << 16) | *(uint16_t*)&h[0];
    r.y = ((uint32_t)*(uint16_t*)&h[3] << 16) | *(uint16_t*)&h[2];
    *(uint2*)(dst + o * 4) = r;
}

// ---------------- depthwise causal conv (K=4) + bias + silu ----------------
// sliding window: 2 channels x 4 consecutive timesteps per thread
__global__ void conv_silu_kernel(const __half* __restrict__ projh,
                                 const float* __restrict__ cw,
                                 const float* __restrict__ cb,
                                 __half* __restrict__ xBCh)
{
    const int NG = CONVDIM / 2;                // channel pairs
    int idx = blockIdx.x * blockDim.x + threadIdx.x;
    if (idx >= (BL / 4) * NG) return;
    int g   = idx % NG;
    int r4  = idx / NG;
    int bl0 = r4 * 4;                          // 4-row group (never crosses batch)
    int l0  = bl0 % LSEQ;
    int ch  = g * 2;

    float4 w0 = *(const float4*)&cw[ch * 4];
    float4 w1 = *(const float4*)&cw[(ch + 1) * 4];
    float wa0[4] = {w0.x, w0.y, w0.z, w0.w};
    float wa1[4] = {w1.x, w1.y, w1.z, w1.w};
    float b0 = cb[ch], b1 = cb[ch + 1];

    float2 xv[7];
#pragma unroll
    for (int t = 0; t < 7; ++t) {
        int l = l0 + t - 3;
        if (l >= 0) {
            __half2 h = *(const __half2*)(projh +
                (size_t)(bl0 + t - 3) * PROJDIM + INTERD + ch);
            xv[t] = __half22float2(h);
        } else {
            xv[t] = make_float2(0.f, 0.f);
        }
    }
#pragma unroll
    for (int q = 0; q < 4; ++q) {
        float a0 = b0, a1 = b1;
#pragma unroll
        for (int k = 0; k < 4; ++k) {
            a0 += wa0[k] * xv[q + k].x;
            a1 += wa1[k] * xv[q + k].y;
        }
        float o0 = a0 / (1.f + __expf(-a0));
        float o1 = a1 / (1.f + __expf(-a1));
        __half2 ov; ov.x = __float2half(o0); ov.y = __float2half(o1);
        *(__half2*)(xBCh + (size_t)(bl0 + q) * CONVDIM + ch) = ov;
    }
}

// ---------------- softplus(dt+bias), per-chunk inclusive cumsum ----------------
__global__ void dt_acum_kernel(const __half* __restrict__ projh,
                               const float* __restrict__ dt_bias,
                               const float* __restrict__ A_log,
                               float* __restrict__ dtv,
                               float* __restrict__ Acum)
{
    int cc = blockIdx.x, h = blockIdx.y, b = blockIdx.z;
    int i  = threadIdx.x;
    int l  = cc * CSIZE + i;
    float d  = __half2float(projh[(size_t)(b * LSEQ + l) * PROJDIM + INTERD + CONVDIM + h])
             + dt_bias[h];
    float sp = (d > 20.f) ? d : log1pf(expf(d));
    dtv[(size_t)(b * LSEQ + l) * NHEADS + h] = sp;
    float dA = sp * (-expf(A_log[h]));
    __shared__ float sbuf[CSIZE];
    sbuf[i] = dA;
    __syncthreads();
    for (int off = 1; off < CSIZE; off <<= 1) {
        float v = sbuf[i];
        if (i >= off) v += sbuf[i - off];
        __syncthreads();
        sbuf[i] = v;
        __syncthreads();
    }
    Acum[(((size_t)b * NHEADS + h) * NCHUNK + cc) * CSIZE + i] = sbuf[i];
}

// =====================================================================
// CB via fp16 mma -> fp16 output
// =====================================================================
#define CB_SMEM (2 * 128 * 256)   // 65536 B
__global__ void __launch_bounds__(256) cb_mma(
    const __half* __restrict__ xBCh, __half* __restrict__ CBh)
{
    extern __shared__ __align__(1024) char sm[];
    __half* Cs = (__half*)sm;
    __half* Bs = (__half*)(sm + 32768);
    const uint32_t sC = smem_u32(Cs), sB = smem_u32(Bs);

    const int bj = blockIdx.x * 128, bi = blockIdx.y * 128;
    const int bc = blockIdx.z;
    const int b = bc / NCHUNK, cc = bc % NCHUNK;
    const int l0 = b * LSEQ + cc * CSIZE;
    const int tid = threadIdx.x, wid = tid >> 5, lane = tid & 31;
    const int wm = (wid & 1) * 64;
    const int wn = (wid >> 1) * 32;

#pragma unroll
    for (int it = 0; it < 8; ++it) {
        int u = tid + it * 256;
        int r = u >> 4, cu = u & 15;
        uint4 vc = *(const uint4*)&xBCh[(size_t)(l0 + bi + r) * CONVDIM + INTERD + NSTATE + cu * 8];
        uint4 vb = *(const uint4*)&xBCh[(size_t)(l0 + bj + r) * CONVDIM + INTERD + cu * 8];
        *(uint4*)((char*)Cs + SW256((uint32_t)(r * 256 + cu * 16))) = vc;
        *(uint4*)((char*)Bs + SW256((uint32_t)(r * 256 + cu * 16))) = vb;
    }
    __syncthreads();

    float c[4][4][4];
#pragma unroll
    for (int mt = 0; mt < 4; ++mt)
#pragma unroll
        for (int nt = 0; nt < 4; ++nt)
#pragma unroll
            for (int q = 0; q < 4; ++q) c[mt][nt][q] = 0.f;

    const int a_row = (lane & 15);
    const int a_ku  = (lane >> 4) * 16;
    const int b_row = ((lane >> 4) & 1) * 8 + (lane & 7);
    const int b_ku  = ((lane >> 3) & 1) * 16;

#pragma unroll
    for (int ks = 0; ks < 8; ++ks) {
        uint32_t a[4][4], bf[4][2];
#pragma unroll
        for (int mt = 0; mt < 4; ++mt) {
            uint32_t off = (uint32_t)((wm + mt * 16 + a_row) * 256 + ks * 32 + a_ku);
            ldsm4(a[mt][0], a[mt][1], a[mt][2], a[mt][3], sC + SW256(off));
        }
#pragma unroll
        for (int pr = 0; pr < 2; ++pr) {
            uint32_t off = (uint32_t)((wn + pr * 16 + b_row) * 256 + ks * 32 + b_ku);
            uint32_t r0, r1, r2, r3;
            ldsm4(r0, r1, r2, r3, sB + SW256(off));
            bf[pr * 2][0] = r0; bf[pr * 2][1] = r1;
            bf[pr * 2 + 1][0] = r2; bf[pr * 2 + 1][1] = r3;
        }
#pragma unroll
        for (int mt = 0; mt < 4; ++mt)
#pragma unroll
            for (int nt = 0; nt < 4; ++nt)
                mma16816(c[mt][nt], a[mt], bf[nt]);
    }

    __half* cbo = CBh + (size_t)bc * CSIZE * CSIZE;
#pragma unroll
    for (int mt = 0; mt < 4; ++mt) {
        int gi = bi + wm + mt * 16 + (lane >> 2);
#pragma unroll
        for (int nt = 0; nt < 4; ++nt) {
            int gj = bj + wn + nt * 8 + (lane & 3) * 2;
            store2(&cbo[(size_t)gi * CSIZE + gj], c[mt][nt][0], c[mt][nt][1]);
            store2(&cbo[(size_t)(gi + 8) * CSIZE + gj], c[mt][nt][2], c[mt][nt][3]);
        }
    }
}

// =====================================================================
// states via mma -> fp16 output
// =====================================================================
#define SSM_SMEM (16384 + 32768 + 512)
__global__ void __launch_bounds__(128) states_mma(
    const __half* __restrict__ xBCh, const float* __restrict__ dtv,
    const float* __restrict__ Acum, __half* __restrict__ statesh)
{
    extern __shared__ __align__(1024) char sm[];
    __half* Xw = (__half*)sm;
    __half* Bs = (__half*)(sm + 16384);
    float*  wv = (float*)(sm + 49152);
    const uint32_t sX = smem_u32(Xw), sB = smem_u32(Bs);

    const int cc = blockIdx.x, h = blockIdx.y, b = blockIdx.z;
    const int tid = threadIdx.x, wid = tid >> 5, lane = tid & 31;
    const float* Ab = Acum + (((size_t)b * NHEADS + h) * NCHUNK + cc) * CSIZE;
    const float AcLast = Ab[CSIZE - 1];
    const int l0 = b * LSEQ + cc * CSIZE;

    float c[4][4][4];
#pragma unroll
    for (int mt = 0; mt < 4; ++mt)
#pragma unroll
        for (int nt = 0; nt < 4; ++nt)
#pragma unroll
            for (int q = 0; q < 4; ++q) c[mt][nt][q] = 0.f;

    for (int jt = 0; jt < CSIZE; jt += 128) {
        wv[tid] = __expf(AcLast - Ab[jt + tid]) * dtv[(size_t)(l0 + jt + tid) * NHEADS + h];
        __syncthreads();
#pragma unroll
        for (int it = 0; it < 8; ++it) {
            int u = tid + it * 128;
            int j = u >> 3, cu = u & 7;
            uint4 v = *(const uint4*)&xBCh[(size_t)(l0 + jt + j) * CONVDIM + h * HDIM + cu * 8];
            __half2 w2 = __float2half2_rn(wv[j]);
            *(uint4*)((char*)Xw + SW128((uint32_t)(j * 128 + cu * 16))) = mul8h(v, w2);
        }
#pragma unroll
        for (int it = 0; it < 16; ++it) {
            int u = tid + it * 128;
            int j = u >> 4, cu = u & 15;
            uint4 v = *(const uint4*)&xBCh[(size_t)(l0 + jt + j) * CONVDIM + INTERD + cu * 8];
            *(uint4*)((char*)Bs + SW256((uint32_t)(j * 256 + cu * 16))) = v;
        }
        __syncthreads();
#pragma unroll
        for (int ks = 0; ks < 8; ++ks) {
            uint32_t a[4][4], bf[4][2];
#pragma unroll
            for (int mt = 0; mt < 4; ++mt) {
                int row = ks * 16 + ((lane >> 4) & 1) * 8 + (lane & 7);
                int col = mt * 16 + ((lane >> 3) & 1) * 8;
                ldsm4t(a[mt][0], a[mt][1], a[mt][2], a[mt][3],
                       sX + SW128((uint32_t)(row * 128 + col * 2)));
            }
#pragma unroll
            for (int nt2 = 0; nt2 < 2; ++nt2) {
                int row = ks * 16 + ((lane >> 3) & 1) * 8 + (lane & 7);
                int col = wid * 32 + nt2 * 16 + (lane >> 4) * 8;
                uint32_t r0, r1, r2, r3;
                ldsm4t(r0, r1, r2, r3, sB + SW256((uint32_t)(row * 256 + col * 2)));
                bf[nt2 * 2][0] = r0; bf[nt2 * 2][1] = r1;
                bf[nt2 * 2 + 1][0] = r2; bf[nt2 * 2 + 1][1] = r3;
            }
#pragma unroll
            for (int mt = 0; mt < 4; ++mt)
#pragma unroll
                for (int nt = 0; nt < 4; ++nt)
                    mma16816(c[mt][nt], a[mt], bf[nt]);
        }
        __syncthreads();
    }
    __half* so = statesh + (((size_t)b * NCHUNK + cc) * NHEADS + h) * (HDIM * NSTATE);
#pragma unroll
    for (int mt = 0; mt < 4; ++mt) {
        int p0 = mt * 16 + (lane >> 2);
#pragma unroll
        for (int nt = 0; nt < 4; ++nt) {
            int n = wid * 32 + nt * 8 + (lane & 3) * 2;
            store2(&so[p0 * NSTATE + n], c[mt][nt][0], c[mt][nt][1]);
            store2(&so[(p0 + 8) * NSTATE + n], c[mt][nt][2], c[mt][nt][3]);
        }
    }
}

// ---------------- inter-chunk recurrence (fp16 states -> fp16 prev) ----------------
__global__ void scan_kernel(const __half* __restrict__ statesh,
                            const float* __restrict__ Acum,
                            __half* __restrict__ prevh)
{
    int h = blockIdx.x, b = blockIdx.y, tid = threadIdx.x;
    float carry[32];
#pragma unroll
    for (int t = 0; t < 32; ++t) carry[t] = 0.f;
    for (int cc = 0; cc < NCHUNK; ++cc) {
        float cd = expf(Acum[(((size_t)b * NHEADS + h) * NCHUNK + cc) * CSIZE + CSIZE - 1]);
        size_t base = (((size_t)b * NCHUNK + cc) * NHEADS + h) * (HDIM * NSTATE);
#pragma unroll
        for (int t = 0; t < 32; ++t) {
            size_t idx = base + tid + t * 256;
            prevh[idx] = __float2half(carry[t]);
            carry[t]   = cd * carry[t] + __half2float(statesh[idx]);
        }
    }
}

// =====================================================================
// Y via mma: Y[i,p] = M @ X + Ce @ prev^T + D*x
// =====================================================================
__global__ void __launch_bounds__(256) y_mma(
    const __half* __restrict__ xBCh, const float* __restrict__ dtv,
    const float* __restrict__ Acum, const __half* __restrict__ CBh,
    const __half* __restrict__ prevh, const float* __restrict__ Dp,
    float* __restrict__ Y)
{
    __shared__ float Ac[CSIZE], dts[CSIZE], rowf[CSIZE], eA[CSIZE], colf[64];
    __shared__ __align__(1024) __half Ms[CSIZE * 64];
    __shared__ __align__(1024) __half Xs[64 * 64];
    const uint32_t sM = smem_u32(Ms), sXs = smem_u32(Xs);

    const int cc = blockIdx.x, h = blockIdx.y, b = blockIdx.z;
    const int tid = threadIdx.x, wid = tid >> 5, lane = tid & 31;
    const int wm = (wid & 3) * 64;
    const int wn = (wid >> 2) * 32;
    const int l0 = b * LSEQ + cc * CSIZE;

    Ac[tid]  = Acum[(((size_t)b * NHEADS + h) * NCHUNK + cc) * CSIZE + tid];
    dts[tid] = dtv[(size_t)(l0 + tid) * NHEADS + h];
    __syncthreads();
    eA[tid] = __expf(Ac[tid]);

    const __half* CBb = CBh + ((size_t)b * NCHUNK + cc) * CSIZE * CSIZE;

    float c[4][4][4];
#pragma unroll
    for (int mt = 0; mt < 4; ++mt)
#pragma unroll
        for (int nt = 0; nt < 4; ++nt)
#pragma unroll
            for (int q = 0; q < 4; ++q) c[mt][nt][q] = 0.f;

    for (int jt = 0; jt < CSIZE; jt += 64) {
        float A_ref = Ac[jt + 63];
        if (tid < 64) colf[tid] = __expf(A_ref - Ac[jt + tid]) * dts[jt + tid];
        rowf[tid] = __expf(Ac[tid] - A_ref);
        __syncthreads();
#pragma unroll
        for (int it = 0; it < 8; ++it) {
            int u = tid + it * 256;
            int i = u >> 3, cu = u & 7;
            float v[8];
            if (i < jt) {
#pragma unroll
                for (int e = 0; e < 8; ++e) v[e] = 0.f;
            } else {
                uint4 cbv = *(const uint4*)&CBb[(size_t)i * CSIZE + jt + cu * 8];
                __half2* ch2 = (__half2*)&cbv;
                float cf[8];
#pragma unroll
                for (int e2 = 0; e2 < 4; ++e2) {
                    float2 f = __half22float2(ch2[e2]);
                    cf[e2 * 2] = f.x; cf[e2 * 2 + 1] = f.y;
                }
                if (i >= jt + 64) {
                    float rf = rowf[i];
#pragma unroll
                    for (int e = 0; e < 8; ++e) v[e] = cf[e] * rf * colf[cu * 8 + e];
                } else {
#pragma unroll
                    for (int e = 0; e < 8; ++e) {
                        int j = jt + cu * 8 + e;
                        v[e] = (j <= i) ? cf[e] * __expf(Ac[i] - Ac[j]) * dts[j] : 0.f;
                    }
                }
            }
            *(uint4*)((char*)Ms + SW128((uint32_t)(i * 128 + cu * 16))) = pack8h(v);
        }
#pragma unroll
        for (int it = 0; it < 2; ++it) {
            int u = tid + it * 256;
            int j = u >> 3, cu = u & 7;
            uint4 v = *(const uint4*)&xBCh[(size_t)(l0 + jt + j) * CONVDIM + h * HDIM + cu * 8];
            *(uint4*)((char*)Xs + SW128((uint32_t)(j * 128 + cu * 16))) = v;
        }
        __syncthreads();
#pragma unroll
        for (int ks = 0; ks < 4; ++ks) {
            uint32_t a[4][4], bf[4][2];
#pragma unroll
            for (int mt = 0; mt < 4; ++mt) {
                int row = wm + mt * 16 + (lane & 15);
                int kb  = ks * 32 + (lane >> 4) * 16;
                ldsm4(a[mt][0], a[mt][1], a[mt][2], a[mt][3],
                      sM + SW128((uint32_t)(row * 128 + kb)));
            }
#pragma unroll
            for (int nt2 = 0; nt2 < 2; ++nt2) {
                int row = ks * 16 + ((lane >> 3) & 1) * 8 + (lane & 7);
                int col = wn + nt2 * 16 + (lane >> 4) * 8;
                uint32_t r0, r1, r2, r3;
                ldsm4t(r0, r1, r2, r3, sXs + SW128((uint32_t)(row * 128 + col * 2)));
                bf[nt2 * 2][0] = r0; bf[nt2 * 2][1] = r1;
                bf[nt2 * 2 + 1][0] = r2; bf[nt2 * 2 + 1][1] = r3;
            }
#pragma unroll
            for (int mt = 0; mt < 4; ++mt)
#pragma unroll
                for (int nt = 0; nt < 4; ++nt)
                    mma16816(c[mt][nt], a[mt], bf[nt]);
        }
        __syncthreads();
    }

    const __half* pvb = prevh + (((size_t)b * NCHUNK + cc) * NHEADS + h) * (HDIM * NSTATE);
    for (int nt0 = 0; nt0 < NSTATE; nt0 += 64) {
#pragma unroll
        for (int it = 0; it < 8; ++it) {
            int u = tid + it * 256;
            int i = u >> 3, cu = u & 7;
            uint4 v = *(const uint4*)&xBCh[(size_t)(l0 + i) * CONVDIM + INTERD + NSTATE + nt0 + cu * 8];
            __half2 ea2 = __float2half2_rn(eA[i]);
            *(uint4*)((char*)Ms + SW128((uint32_t)(i * 128 + cu * 16))) = mul8h(v, ea2);
        }
#pragma unroll
        for (int it = 0; it < 2; ++it) {
            int u = tid + it * 256;
            int p = u >> 3, cu = u & 7;
            uint4 v = *(const uint4*)(pvb + (size_t)p * NSTATE + nt0 + cu * 8);
            *(uint4*)((char*)Xs + SW128((uint32_t)(p * 128 + cu * 16))) = v;
        }
        __syncthreads();
#pragma unroll
        for (int ks = 0; ks < 4; ++ks) {
            uint32_t a[4][4], bf[4][2];
#pragma unroll
            for (int mt = 0; mt < 4; ++mt) {
                int row = wm + mt * 16 + (lane & 15);
                int kb  = ks * 32 + (lane >> 4) * 16;
                ldsm4(a[mt][0], a[mt][1], a[mt][2], a[mt][3],
                      sM + SW128((uint32_t)(row * 128 + kb)));
            }
#pragma unroll
            for (int nt2 = 0; nt2 < 2; ++nt2) {
                int prow = wn + nt2 * 16 + ((lane >> 4) & 1) * 8 + (lane & 7);
                int kb   = ks * 32 + ((lane >> 3) & 1) * 16;
                uint32_t r0, r1, r2, r3;
                ldsm4(r0, r1, r2, r3, sXs + SW128((uint32_t)(prow * 128 + kb)));
                bf[nt2 * 2][0] = r0; bf[nt2 * 2][1] = r1;
                bf[nt2 * 2 + 1][0] = r2; bf[nt2 * 2 + 1][1] = r3;
            }
#pragma unroll
            for (int mt = 0; mt < 4; ++mt)
#pragma unroll
                for (int nt = 0; nt < 4; ++nt)
                    mma16816(c[mt][nt], a[mt], bf[nt]);
        }
        __syncthreads();
    }

    float Dh = Dp[h];
#pragma unroll
    for (int mt = 0; mt < 4; ++mt) {
        int i0 = wm + mt * 16 + (lane >> 2);
#pragma unroll
        for (int nt = 0; nt < 4; ++nt) {
            int p = wn + nt * 8 + (lane & 3) * 2;
#pragma unroll
            for (int half = 0; half < 2; ++half) {
                int i = i0 + half * 8;
                __half2 xh = *(const __half2*)&xBCh[(size_t)(l0 + i) * CONVDIM + h * HDIM + p];
                float2 xv = __half22float2(xh);
                float2 ov;
                ov.x = c[mt][nt][half * 2 + 0] + Dh * xv.x;
                ov.y = c[mt][nt][half * 2 + 1] + Dh * xv.y;
                *(float2*)&Y[(size_t)(l0 + i) * INTERD + h * HDIM + p] = ov;
            }
        }
    }
}

// ---------------- gate (silu, fp16 in) + RMSNorm -> fp16 Y2 ----------------
__global__ void gate_rms_kernel(const __half* __restrict__ projh,
                                const float* __restrict__ norm_w,
                                const float* __restrict__ Y,
                                __half* __restrict__ Y2)
{
    int row = blockIdx.x, tid = threadIdx.x;
    const __half* gr = projh + (size_t)row * PROJDIM;
    const float* yr = Y + (size_t)row * INTERD;
    float yv[16];
    float ss = 0.f;
#pragma unroll
    for (int t = 0; t < 16; ++t) {
        int e = tid + t * 256;
        float g = __half2float(gr[e]);
        float v = yr[e] * (g / (1.f + __expf(-g)));
        yv[t] = v;
        ss += v * v;
    }
    __shared__ float red[8];
#pragma unroll
    for (int o = 16; o > 0; o >>= 1) ss += __shfl_xor_sync(0xffffffff, ss, o);
    if ((tid & 31) == 0) red[tid >> 5] = ss;
    __syncthreads();
    float tot = 0.f;
#pragma unroll
    for (int w = 0; w < 8; ++w) tot += red[w];
    float scale = rsqrtf(tot / (float)INTERD + EPSV);
    __half* y2r = Y2 + (size_t)row * INTERD;
#pragma unroll
    for (int t = 0; t < 16; ++t) {
        int e = tid + t * 256;
        y2r[e] = __float2half(yv[t] * scale * norm_w[e]);
    }
}

// ---------------- launch ----------------
extern "C" void kernel_launch(void* const* d_in, const int* in_sizes, int n_in,
                              void* d_out, int out_size)
{
    const float* hs      = (const float*)d_in[0];
    const float* W_in    = (const float*)d_in[1];
    const float* conv_w  = (const float*)d_in[2];
    const float* conv_b  = (const float*)d_in[3];
    const float* dt_bias = (const float*)d_in[4];
    const float* A_log   = (const float*)d_in[5];
    const float* Dp      = (const float*)d_in[6];
    const float* norm_w  = (const float*)d_in[7];
    const float* W_out   = (const float*)d_in[8];
    float* out = (float*)d_out;

    float *dtv, *Acum, *Y;
    __half *projh, *xBCh, *CBh, *statesh, *prevh, *A2, *Win2, *Y2, *Wout2;
    cudaGetSymbolAddress((void**)&projh,   g_projh);
    cudaGetSymbolAddress((void**)&xBCh,    g_xBCh);
    cudaGetSymbolAddress((void**)&dtv,     g_dtv);
    cudaGetSymbolAddress((void**)&Acum,    g_Acum);
    cudaGetSymbolAddress((void**)&CBh,     g_CBh);
    cudaGetSymbolAddress((void**)&statesh, g_statesh);
    cudaGetSymbolAddress((void**)&prevh,   g_prevh);
    cudaGetSymbolAddress((void**)&Y,       g_Y);
    cudaGetSymbolAddress((void**)&A2,      g_A2);
    cudaGetSymbolAddress((void**)&Win2,    g_Win2);
    cudaGetSymbolAddress((void**)&Y2,      g_Y2);
    cudaGetSymbolAddress((void**)&Wout2,   g_Wout2);

    cudaFuncSetAttribute(gemm_fp16_mma<__half>,
                         cudaFuncAttributeMaxDynamicSharedMemorySize, TSMEM);
    cudaFuncSetAttribute(gemm_fp16_mma<float>,
                         cudaFuncAttributeMaxDynamicSharedMemorySize, TSMEM);
    cudaFuncSetAttribute(states_mma,
                         cudaFuncAttributeMaxDynamicSharedMemorySize, SSM_SMEM);
    cudaFuncSetAttribute(cb_mma,
                         cudaFuncAttributeMaxDynamicSharedMemorySize, CB_SMEM);

    // 0) fused fp32 -> fp16 conversion (hs, W_in, W_out)
    {
        long long tot = CVT_T1 + CVT_T2 + CVT_T3;
        cvt_all_kernel<<<(unsigned)((tot + 255) / 256), 256>>>(
            hs, W_in, W_out, A2, Win2, Wout2);
    }

    // 1) proj = hs @ W_in^T  (fp16 output)
    gemm_fp16_mma<__half><<<dim3(BL / 128, (PROJDIM + 127) / 128), 256, TSMEM>>>(
        A2, Win2, projh, BL, PROJDIM, DMODEL, PROJDIM);

    // 2) conv + silu -> fp16 xBC (sliding window, 2ch x 4 timesteps/thread)
    {
        int total = (BL / 4) * (CONVDIM / 2);
        conv_silu_kernel<<<(total + 255) / 256, 256>>>(projh, conv_w, conv_b, xBCh);
    }

    // 3) softplus(dt) + cumsum
    dt_acum_kernel<<<dim3(NCHUNK, NHEADS, BATCH), CSIZE>>>(projh, dt_bias, A_log, dtv, Acum);

    // 4) CB = C . B^T via fp16 mma -> fp16
    cb_mma<<<dim3(2, 2, BATCH * NCHUNK), 256, CB_SMEM>>>(xBCh, CBh);

    // 5) states via mma -> fp16
    states_mma<<<dim3(NCHUNK, NHEADS, BATCH), 128, SSM_SMEM>>>(xBCh, dtv, Acum, statesh);

    // 6) scan -> fp16 prev
    scan_kernel<<<dim3(NHEADS, BATCH), 256>>>(statesh, Acum, prevh);

    // 7) Y via mma (Ydiag + Yoff + D*x)
    y_mma<<<dim3(NCHUNK, NHEADS, BATCH), 256>>>(xBCh, dtv, Acum, CBh, prevh, Dp, Y);

    // 8) gate + RMSNorm -> fp16
    gate_rms_kernel<<<BL, 256>>>(projh, norm_w, Y, Y2);

    // 9) out = Y @ W_out^T (fp32 output)
    gemm_fp16_mma<float><<<dim3(BL / 128, DMODEL / 128), 256, TSMEM>>>(
        Y2, Wout2, out, BL, DMODEL, INTERD, DMODEL);
}

// round 15
// speedup vs baseline: 1.1160x; 1.0135x over previous
#include <cuda_runtime.h>
#include <cuda_fp16.h>
#include <cstdint>

// ---------------- problem constants ----------------
#define BATCH    2
#define LSEQ     2048
#define DMODEL   2048
#define INTERD   4096
#define NHEADS   64
#define HDIM     64
#define NSTATE   128
#define KCONV    4
#define CSIZE    256
#define NCHUNK   (LSEQ / CSIZE)                 // 8
#define CONVDIM  (INTERD + 2 * NSTATE)          // 4352
#define PROJDIM  (INTERD + CONVDIM + NHEADS)    // 8512
#define BL       (BATCH * LSEQ)                 // 4096
#define EPSV     1e-5f

// ---------------- device scratch (static; no allocs allowed) ----------------
__device__ __half g_projh [(size_t)BL * PROJDIM];
__device__ __half g_xBCh  [(size_t)BL * CONVDIM];
__device__ float g_dtv    [(size_t)BL * NHEADS];
__device__ float g_Acum   [(size_t)BATCH * NHEADS * NCHUNK * CSIZE];
__device__ __half g_CBh   [(size_t)BATCH * NCHUNK * CSIZE * CSIZE];
__device__ __half g_statesh[(size_t)BATCH * NCHUNK * NHEADS * HDIM * NSTATE];
__device__ __half g_prevh [(size_t)BATCH * NCHUNK * NHEADS * HDIM * NSTATE];
__device__ __half g_Yh    [(size_t)BL * INTERD];
__device__ __half g_A2    [(size_t)BL * DMODEL];
__device__ __half g_Win2  [(size_t)PROJDIM * DMODEL];
__device__ __half g_Y2    [(size_t)BL * INTERD];
__device__ __half g_Wout2 [(size_t)DMODEL * INTERD];

// =====================================================================
// common mma helpers
// =====================================================================
__device__ __forceinline__ uint32_t smem_u32(const void* p) {
    return (uint32_t)__cvta_generic_to_shared(p);
}
#define SW128(o) ((o) ^ (((o) >> 3) & 0x70))
#define SW256(o) ((o) ^ (((o) >> 4) & 0x70))

__device__ __forceinline__ void cp_async16(uint32_t d, const void* g, int sz) {
    asm volatile("cp.async.cg.shared.global [%0], [%1], 16, %2;"
                 :: "r"(d), "l"(g), "r"(sz) : "memory");
}
#define CP_COMMIT() asm volatile("cp.async.commit_group;" ::: "memory")
#define CP_WAIT1()  asm volatile("cp.async.wait_group 1;" ::: "memory")

__device__ __forceinline__ void ldsm4(uint32_t& r0, uint32_t& r1, uint32_t& r2,
                                      uint32_t& r3, uint32_t a) {
    asm volatile("ldmatrix.sync.aligned.m8n8.x4.shared.b16 {%0,%1,%2,%3}, [%4];"
                 : "=r"(r0), "=r"(r1), "=r"(r2), "=r"(r3) : "r"(a));
}
__device__ __forceinline__ void ldsm4t(uint32_t& r0, uint32_t& r1, uint32_t& r2,
                                       uint32_t& r3, uint32_t a) {
    asm volatile("ldmatrix.sync.aligned.m8n8.x4.trans.shared.b16 {%0,%1,%2,%3}, [%4];"
                 : "=r"(r0), "=r"(r1), "=r"(r2), "=r"(r3) : "r"(a));
}
__device__ __forceinline__ void mma16816(float* c, const uint32_t* a, const uint32_t* b) {
    asm volatile(
        "mma.sync.aligned.m16n8k16.row.col.f32.f16.f16.f32 "
        "{%0,%1,%2,%3}, {%4,%5,%6,%7}, {%8,%9}, {%0,%1,%2,%3};"
        : "+f"(c[0]), "+f"(c[1]), "+f"(c[2]), "+f"(c[3])
        : "r"(a[0]), "r"(a[1]), "r"(a[2]), "r"(a[3]), "r"(b[0]), "r"(b[1]));
}

__device__ __forceinline__ uint4 pack8h(const float* v) {
    __half h[8];
#pragma unroll
    for (int e = 0; e < 8; ++e) h[e] = __float2half(v[e]);
    uint4 r;
    r.x = ((uint32_t)*(uint16_t*)&h[1] << 16) | *(uint16_t*)&h[0];
    r.y = ((uint32_t)*(uint16_t*)&h[3] << 16) | *(uint16_t*)&h[2];
    r.z = ((uint32_t)*(uint16_t*)&h[5] << 16) | *(uint16_t*)&h[4];
    r.w = ((uint32_t)*(uint16_t*)&h[7] << 16) | *(uint16_t*)&h[6];
    return r;
}
__device__ __forceinline__ uint4 mul8h(uint4 v, __half2 w) {
    __half2* p = (__half2*)&v;
    p[0] = __hmul2(p[0], w); p[1] = __hmul2(p[1], w);
    p[2] = __hmul2(p[2], w); p[3] = __hmul2(p[3], w);
    return v;
}

__device__ __forceinline__ void store2(float* p, float a, float b) {
    *(float2*)p = make_float2(a, b);
}
__device__ __forceinline__ void store2(__half* p, float a, float b) {
    __half2 h; h.x = __float2half(a); h.y = __float2half(b);
    *(__half2*)p = h;
}

// =====================================================================
// big fp16 GEMM: BM=BN=128, BK=64, 3 stages, 256 threads, 2 CTAs/SM
// =====================================================================
#define TSTAGE_B (128 * 128 * 2)             // 32768
#define TNSTG    3
#define TSMEM    (TNSTG * TSTAGE_B)          // 98304

template <typename TOUT>
__global__ void __launch_bounds__(256, 2) gemm_fp16_mma(
    const __half* __restrict__ A, const __half* __restrict__ Bm,
    TOUT* __restrict__ C, int M, int N, int K, int ldc)
{
    extern __shared__ __align__(1024) char smem[];
    const uint32_t sbase = smem_u32(smem);
    const int tid  = threadIdx.x;
    const int wid  = tid >> 5, lane = tid & 31;
    const int bm   = blockIdx.x * 128, bn = blockIdx.y * 128;
    const int wm   = (wid & 1) * 64;
    const int wn   = (wid >> 1) * 32;
    const int KT   = K >> 6;

    float c[4][4][4];
#pragma unroll
    for (int mt = 0; mt < 4; ++mt)
#pragma unroll
        for (int nt = 0; nt < 4; ++nt)
#pragma unroll
            for (int q = 0; q < 4; ++q) c[mt][nt][q] = 0.f;

#define LOAD_STAGE(kt, s) do {                                               \
    uint32_t st_ = sbase + (s) * TSTAGE_B;                                   \
    _Pragma("unroll")                                                        \
    for (int i_ = 0; i_ < 4; ++i_) {                                         \
        int u_ = tid + i_ * 256;                                             \
        int r_ = u_ >> 3, lu_ = u_ & 7;                                      \
        uint32_t d_ = st_ + SW128((uint32_t)(r_ * 128 + lu_ * 16));          \
        const void* g_ = (const char*)A +                                    \
            (((size_t)(bm + r_) * K + (size_t)(kt) * 64 + lu_ * 8) << 1);    \
        cp_async16(d_, g_, 16);                                              \
    }                                                                        \
    _Pragma("unroll")                                                        \
    for (int i_ = 0; i_ < 4; ++i_) {                                         \
        int u_ = tid + i_ * 256;                                             \
        int r_ = u_ >> 3, lu_ = u_ & 7;                                      \
        int gn_ = bn + r_;                                                   \
        uint32_t d_ = st_ + 16384 + SW128((uint32_t)(r_ * 128 + lu_ * 16));  \
        const void* g_ = (const char*)Bm +                                   \
            (((size_t)gn_ * K + (size_t)(kt) * 64 + lu_ * 8) << 1);          \
        cp_async16(d_, g_, gn_ < N ? 16 : 0);                                \
    }                                                                        \
} while (0)

    LOAD_STAGE(0, 0); CP_COMMIT();
    LOAD_STAGE(1, 1); CP_COMMIT();

    const int a_row = (lane & 15);
    const int a_ku  = (lane >> 4) * 16;
    const int b_row = ((lane >> 4) & 1) * 8 + (lane & 7);
    const int b_ku  = ((lane >> 3) & 1) * 16;

    for (int kt = 0; kt < KT; ++kt) {
        const int s = kt % 3;
        CP_WAIT1();
        __syncthreads();
        if (kt + 2 < KT) LOAD_STAGE(kt + 2, (kt + 2) % 3);
        CP_COMMIT();

        const uint32_t stA = sbase + s * TSTAGE_B;
        const uint32_t stB = stA + 16384;
#pragma unroll
        for (int ks = 0; ks < 4; ++ks) {
            uint32_t a[4][4], b[4][2];
#pragma unroll
            for (int mt = 0; mt < 4; ++mt) {
                uint32_t off = (uint32_t)((wm + mt * 16 + a_row) * 128 + ks * 32 + a_ku);
                ldsm4(a[mt][0], a[mt][1], a[mt][2], a[mt][3], stA + SW128(off));
            }
#pragma unroll
            for (int pr = 0; pr < 2; ++pr) {
                uint32_t off = (uint32_t)((wn + pr * 16 + b_row) * 128 + ks * 32 + b_ku);
                uint32_t r0, r1, r2, r3;
                ldsm4(r0, r1, r2, r3, stB + SW128(off));
                b[pr * 2][0] = r0; b[pr * 2][1] = r1;
                b[pr * 2 + 1][0] = r2; b[pr * 2 + 1][1] = r3;
            }
#pragma unroll
            for (int mt = 0; mt < 4; ++mt)
#pragma unroll
                for (int nt = 0; nt < 4; ++nt)
                    mma16816(c[mt][nt], a[mt], b[nt]);
        }
    }

#pragma unroll
    for (int mt = 0; mt < 4; ++mt) {
        int r0 = bm + wm + mt * 16 + (lane >> 2);
#pragma unroll
        for (int nt = 0; nt < 4; ++nt) {
            int col = bn + wn + nt * 8 + (lane & 3) * 2;
            if (col < N) {
                store2(&C[(size_t)r0 * ldc + col], c[mt][nt][0], c[mt][nt][1]);
                store2(&C[(size_t)(r0 + 8) * ldc + col], c[mt][nt][2], c[mt][nt][3]);
            }
        }
    }
}

// ---------------- fused fp32 -> fp16 convert of hs, W_in, W_out ----------------
#define CVT_T1 ((long long)BL * DMODEL / 4)
#define CVT_T2 ((long long)PROJDIM * DMODEL / 4)
#define CVT_T3 ((long long)DMODEL * INTERD / 4)
__global__ void cvt_all_kernel(const float* __restrict__ hs,
                               const float* __restrict__ W_in,
                               const float* __restrict__ W_out,
                               __half* __restrict__ A2,
                               __half* __restrict__ Win2,
                               __half* __restrict__ Wout2)
{
    long long t = (long long)blockIdx.x * blockDim.x + threadIdx.x;
    const float* src; __half* dst; long long o;
    if (t < CVT_T1) { src = hs; dst = A2; o = t; }
    else if (t < CVT_T1 + CVT_T2) { src = W_in; dst = Win2; o = t - CVT_T1; }
    else if (t < CVT_T1 + CVT_T2 + CVT_T3) { src = W_out; dst = Wout2; o = t - CVT_T1 - CVT_T2; }
    else return;
    float4 a = *(const float4*)(src + o * 4);
    __half h[4];
    h[0] = __float2half(a.x); h[1] = __float2half(a.y);
    h[2] = __float2half(a.z); h[3] = __float2half(a.w);
    uint2 r;
    r.x = ((uint32_t)*(uint16_t*)&h[1] << 16) | *(uint16_t*)&h[0];
    r.y = ((uint32_t)*(uint16_t*)&h[3] << 16) | *(uint16_t*)&h[2];
    *(uint2*)(dst + o * 4) = r;
}

// ---------------- depthwise causal conv (K=4) + bias + silu ----------------
// sliding window: 2 channels x 4 consecutive timesteps per thread
__global__ void conv_silu_kernel(const __half* __restrict__ projh,
                                 const float* __restrict__ cw,
                                 const float* __restrict__ cb,
                                 __half* __restrict__ xBCh)
{
    const int NG = CONVDIM / 2;
    int idx = blockIdx.x * blockDim.x + threadIdx.x;
    if (idx >= (BL / 4) * NG) return;
    int g   = idx % NG;
    int r4  = idx / NG;
    int bl0 = r4 * 4;
    int l0  = bl0 % LSEQ;
    int ch  = g * 2;

    float4 w0 = *(const float4*)&cw[ch * 4];
    float4 w1 = *(const float4*)&cw[(ch + 1) * 4];
    float wa0[4] = {w0.x, w0.y, w0.z, w0.w};
    float wa1[4] = {w1.x, w1.y, w1.z, w1.w};
    float b0 = cb[ch], b1 = cb[ch + 1];

    float2 xv[7];
#pragma unroll
    for (int t = 0; t < 7; ++t) {
        int l = l0 + t - 3;
        if (l >= 0) {
            __half2 h = *(const __half2*)(projh +
                (size_t)(bl0 + t - 3) * PROJDIM + INTERD + ch);
            xv[t] = __half22float2(h);
        } else {
            xv[t] = make_float2(0.f, 0.f);
        }
    }
#pragma unroll
    for (int q = 0; q < 4; ++q) {
        float a0 = b0, a1 = b1;
#pragma unroll
        for (int k = 0; k < 4; ++k) {
            a0 += wa0[k] * xv[q + k].x;
            a1 += wa1[k] * xv[q + k].y;
        }
        float o0 = a0 / (1.f + __expf(-a0));
        float o1 = a1 / (1.f + __expf(-a1));
        __half2 ov; ov.x = __float2half(o0); ov.y = __float2half(o1);
        *(__half2*)(xBCh + (size_t)(bl0 + q) * CONVDIM + ch) = ov;
    }
}

// ---------------- softplus(dt+bias), per-chunk inclusive cumsum (warp scan) ----------------
__global__ void dt_acum_kernel(const __half* __restrict__ projh,
                               const float* __restrict__ dt_bias,
                               const float* __restrict__ A_log,
                               float* __restrict__ dtv,
                               float* __restrict__ Acum)
{
    int cc = blockIdx.x, h = blockIdx.y, b = blockIdx.z;
    int i  = threadIdx.x;
    int wid = i >> 5, lane = i & 31;
    int l  = cc * CSIZE + i;
    float d  = __half2float(projh[(size_t)(b * LSEQ + l) * PROJDIM + INTERD + CONVDIM + h])
             + dt_bias[h];
    float sp = (d > 20.f) ? d : log1pf(expf(d));
    dtv[(size_t)(b * LSEQ + l) * NHEADS + h] = sp;
    float v = sp * (-expf(A_log[h]));
#pragma unroll
    for (int o = 1; o < 32; o <<= 1) {
        float t = __shfl_up_sync(0xffffffff, v, o);
        if (lane >= o) v += t;
    }
    __shared__ float wsum[8], wpre[8];
    if (lane == 31) wsum[wid] = v;
    __syncthreads();
    if (i < 8) {
        float s = wsum[i];
#pragma unroll
        for (int o = 1; o < 8; o <<= 1) {
            float t = __shfl_up_sync(0xff, s, o);
            if (i >= o) s += t;
        }
        wpre[i] = s - wsum[i];
    }
    __syncthreads();
    Acum[(((size_t)b * NHEADS + h) * NCHUNK + cc) * CSIZE + i] = v + wpre[wid];
}

// =====================================================================
// CB via fp16 mma -> fp16 output
// =====================================================================
#define CB_SMEM (2 * 128 * 256)   // 65536 B
__global__ void __launch_bounds__(256) cb_mma(
    const __half* __restrict__ xBCh, __half* __restrict__ CBh)
{
    extern __shared__ __align__(1024) char sm[];
    __half* Cs = (__half*)sm;
    __half* Bs = (__half*)(sm + 32768);
    const uint32_t sC = smem_u32(Cs), sB = smem_u32(Bs);

    const int bj = blockIdx.x * 128, bi = blockIdx.y * 128;
    const int bc = blockIdx.z;
    const int b = bc / NCHUNK, cc = bc % NCHUNK;
    const int l0 = b * LSEQ + cc * CSIZE;
    const int tid = threadIdx.x, wid = tid >> 5, lane = tid & 31;
    const int wm = (wid & 1) * 64;
    const int wn = (wid >> 1) * 32;

#pragma unroll
    for (int it = 0; it < 8; ++it) {
        int u = tid + it * 256;
        int r = u >> 4, cu = u & 15;
        uint4 vc = *(const uint4*)&xBCh[(size_t)(l0 + bi + r) * CONVDIM + INTERD + NSTATE + cu * 8];
        uint4 vb = *(const uint4*)&xBCh[(size_t)(l0 + bj + r) * CONVDIM + INTERD + cu * 8];
        *(uint4*)((char*)Cs + SW256((uint32_t)(r * 256 + cu * 16))) = vc;
        *(uint4*)((char*)Bs + SW256((uint32_t)(r * 256 + cu * 16))) = vb;
    }
    __syncthreads();

    float c[4][4][4];
#pragma unroll
    for (int mt = 0; mt < 4; ++mt)
#pragma unroll
        for (int nt = 0; nt < 4; ++nt)
#pragma unroll
            for (int q = 0; q < 4; ++q) c[mt][nt][q] = 0.f;

    const int a_row = (lane & 15);
    const int a_ku  = (lane >> 4) * 16;
    const int b_row = ((lane >> 4) & 1) * 8 + (lane & 7);
    const int b_ku  = ((lane >> 3) & 1) * 16;

#pragma unroll
    for (int ks = 0; ks < 8; ++ks) {
        uint32_t a[4][4], bf[4][2];
#pragma unroll
        for (int mt = 0; mt < 4; ++mt) {
            uint32_t off = (uint32_t)((wm + mt * 16 + a_row) * 256 + ks * 32 + a_ku);
            ldsm4(a[mt][0], a[mt][1], a[mt][2], a[mt][3], sC + SW256(off));
        }
#pragma unroll
        for (int pr = 0; pr < 2; ++pr) {
            uint32_t off = (uint32_t)((wn + pr * 16 + b_row) * 256 + ks * 32 + b_ku);
            uint32_t r0, r1, r2, r3;
            ldsm4(r0, r1, r2, r3, sB + SW256(off));
            bf[pr * 2][0] = r0; bf[pr * 2][1] = r1;
            bf[pr * 2 + 1][0] = r2; bf[pr * 2 + 1][1] = r3;
        }
#pragma unroll
        for (int mt = 0; mt < 4; ++mt)
#pragma unroll
            for (int nt = 0; nt < 4; ++nt)
                mma16816(c[mt][nt], a[mt], bf[nt]);
    }

    __half* cbo = CBh + (size_t)bc * CSIZE * CSIZE;
#pragma unroll
    for (int mt = 0; mt < 4; ++mt) {
        int gi = bi + wm + mt * 16 + (lane >> 2);
#pragma unroll
        for (int nt = 0; nt < 4; ++nt) {
            int gj = bj + wn + nt * 8 + (lane & 3) * 2;
            store2(&cbo[(size_t)gi * CSIZE + gj], c[mt][nt][0], c[mt][nt][1]);
            store2(&cbo[(size_t)(gi + 8) * CSIZE + gj], c[mt][nt][2], c[mt][nt][3]);
        }
    }
}

// =====================================================================
// states via mma -> fp16 output
// =====================================================================
#define SSM_SMEM (16384 + 32768 + 512)
__global__ void __launch_bounds__(128) states_mma(
    const __half* __restrict__ xBCh, const float* __restrict__ dtv,
    const float* __restrict__ Acum, __half* __restrict__ statesh)
{
    extern __shared__ __align__(1024) char sm[];
    __half* Xw = (__half*)sm;
    __half* Bs = (__half*)(sm + 16384);
    float*  wv = (float*)(sm + 49152);
    const uint32_t sX = smem_u32(Xw), sB = smem_u32(Bs);

    const int cc = blockIdx.x, h = blockIdx.y, b = blockIdx.z;
    const int tid = threadIdx.x, wid = tid >> 5, lane = tid & 31;
    const float* Ab = Acum + (((size_t)b * NHEADS + h) * NCHUNK + cc) * CSIZE;
    const float AcLast = Ab[CSIZE - 1];
    const int l0 = b * LSEQ + cc * CSIZE;

    float c[4][4][4];
#pragma unroll
    for (int mt = 0; mt < 4; ++mt)
#pragma unroll
        for (int nt = 0; nt < 4; ++nt)
#pragma unroll
            for (int q = 0; q < 4; ++q) c[mt][nt][q] = 0.f;

    for (int jt = 0; jt < CSIZE; jt += 128) {
        wv[tid] = __expf(AcLast - Ab[jt + tid]) * dtv[(size_t)(l0 + jt + tid) * NHEADS + h];
        __syncthreads();
#pragma unroll
        for (int it = 0; it < 8; ++it) {
            int u = tid + it * 128;
            int j = u >> 3, cu = u & 7;
            uint4 v = *(const uint4*)&xBCh[(size_t)(l0 + jt + j) * CONVDIM + h * HDIM + cu * 8];
            __half2 w2 = __float2half2_rn(wv[j]);
            *(uint4*)((char*)Xw + SW128((uint32_t)(j * 128 + cu * 16))) = mul8h(v, w2);
        }
#pragma unroll
        for (int it = 0; it < 16; ++it) {
            int u = tid + it * 128;
            int j = u >> 4, cu = u & 15;
            uint4 v = *(const uint4*)&xBCh[(size_t)(l0 + jt + j) * CONVDIM + INTERD + cu * 8];
            *(uint4*)((char*)Bs + SW256((uint32_t)(j * 256 + cu * 16))) = v;
        }
        __syncthreads();
#pragma unroll
        for (int ks = 0; ks < 8; ++ks) {
            uint32_t a[4][4], bf[4][2];
#pragma unroll
            for (int mt = 0; mt < 4; ++mt) {
                int row = ks * 16 + ((lane >> 4) & 1) * 8 + (lane & 7);
                int col = mt * 16 + ((lane >> 3) & 1) * 8;
                ldsm4t(a[mt][0], a[mt][1], a[mt][2], a[mt][3],
                       sX + SW128((uint32_t)(row * 128 + col * 2)));
            }
#pragma unroll
            for (int nt2 = 0; nt2 < 2; ++nt2) {
                int row = ks * 16 + ((lane >> 3) & 1) * 8 + (lane & 7);
                int col = wid * 32 + nt2 * 16 + (lane >> 4) * 8;
                uint32_t r0, r1, r2, r3;
                ldsm4t(r0, r1, r2, r3, sB + SW256((uint32_t)(row * 256 + col * 2)));
                bf[nt2 * 2][0] = r0; bf[nt2 * 2][1] = r1;
                bf[nt2 * 2 + 1][0] = r2; bf[nt2 * 2 + 1][1] = r3;
            }
#pragma unroll
            for (int mt = 0; mt < 4; ++mt)
#pragma unroll
                for (int nt = 0; nt < 4; ++nt)
                    mma16816(c[mt][nt], a[mt], bf[nt]);
        }
        __syncthreads();
    }
    __half* so = statesh + (((size_t)b * NCHUNK + cc) * NHEADS + h) * (HDIM * NSTATE);
#pragma unroll
    for (int mt = 0; mt < 4; ++mt) {
        int p0 = mt * 16 + (lane >> 2);
#pragma unroll
        for (int nt = 0; nt < 4; ++nt) {
            int n = wid * 32 + nt * 8 + (lane & 3) * 2;
            store2(&so[p0 * NSTATE + n], c[mt][nt][0], c[mt][nt][1]);
            store2(&so[(p0 + 8) * NSTATE + n], c[mt][nt][2], c[mt][nt][3]);
        }
    }
}

// ---------------- inter-chunk recurrence (fp16 states -> fp16 prev) ----------------
__global__ void scan_kernel(const __half* __restrict__ statesh,
                            const float* __restrict__ Acum,
                            __half* __restrict__ prevh)
{
    int h = blockIdx.x, b = blockIdx.y, tid = threadIdx.x;
    float carry[32];
#pragma unroll
    for (int t = 0; t < 32; ++t) carry[t] = 0.f;
    for (int cc = 0; cc < NCHUNK; ++cc) {
        float cd = expf(Acum[(((size_t)b * NHEADS + h) * NCHUNK + cc) * CSIZE + CSIZE - 1]);
        size_t base = (((size_t)b * NCHUNK + cc) * NHEADS + h) * (HDIM * NSTATE);
#pragma unroll
        for (int t = 0; t < 32; ++t) {
            size_t idx = base + tid + t * 256;
            prevh[idx] = __float2half(carry[t]);
            carry[t]   = cd * carry[t] + __half2float(statesh[idx]);
        }
    }
}

// =====================================================================
// Y via mma: Y[i,p] = M @ X + Ce @ prev^T + D*x  (fp16 output)
// =====================================================================
__global__ void __launch_bounds__(256) y_mma(
    const __half* __restrict__ xBCh, const float* __restrict__ dtv,
    const float* __restrict__ Acum, const __half* __restrict__ CBh,
    const __half* __restrict__ prevh, const float* __restrict__ Dp,
    __half* __restrict__ Yh)
{
    __shared__ float Ac[CSIZE], dts[CSIZE], rowf[CSIZE], eA[CSIZE], colf[64];
    __shared__ __align__(1024) __half Ms[CSIZE * 64];
    __shared__ __align__(1024) __half Xs[64 * 64];
    const uint32_t sM = smem_u32(Ms), sXs = smem_u32(Xs);

    const int cc = blockIdx.x, h = blockIdx.y, b = blockIdx.z;
    const int tid = threadIdx.x, wid = tid >> 5, lane = tid & 31;
    const int wm = (wid & 3) * 64;
    const int wn = (wid >> 2) * 32;
    const int l0 = b * LSEQ + cc * CSIZE;

    Ac[tid]  = Acum[(((size_t)b * NHEADS + h) * NCHUNK + cc) * CSIZE + tid];
    dts[tid] = dtv[(size_t)(l0 + tid) * NHEADS + h];
    __syncthreads();
    eA[tid] = __expf(Ac[tid]);

    const __half* CBb = CBh + ((size_t)b * NCHUNK + cc) * CSIZE * CSIZE;

    float c[4][4][4];
#pragma unroll
    for (int mt = 0; mt < 4; ++mt)
#pragma unroll
        for (int nt = 0; nt < 4; ++nt)
#pragma unroll
            for (int q = 0; q < 4; ++q) c[mt][nt][q] = 0.f;

    for (int jt = 0; jt < CSIZE; jt += 64) {
        float A_ref = Ac[jt + 63];
        if (tid < 64) colf[tid] = __expf(A_ref - Ac[jt + tid]) * dts[jt + tid];
        rowf[tid] = __expf(Ac[tid] - A_ref);
        __syncthreads();
#pragma unroll
        for (int it = 0; it < 8; ++it) {
            int u = tid + it * 256;
            int i = u >> 3, cu = u & 7;
            float v[8];
            if (i < jt) {
#pragma unroll
                for (int e = 0; e < 8; ++e) v[e] = 0.f;
            } else {
                uint4 cbv = *(const uint4*)&CBb[(size_t)i * CSIZE + jt + cu * 8];
                __half2* ch2 = (__half2*)&cbv;
                float cf[8];
#pragma unroll
                for (int e2 = 0; e2 < 4; ++e2) {
                    float2 f = __half22float2(ch2[e2]);
                    cf[e2 * 2] = f.x; cf[e2 * 2 + 1] = f.y;
                }
                if (i >= jt + 64) {
                    float rf = rowf[i];
#pragma unroll
                    for (int e = 0; e < 8; ++e) v[e] = cf[e] * rf * colf[cu * 8 + e];
                } else {
#pragma unroll
                    for (int e = 0; e < 8; ++e) {
                        int j = jt + cu * 8 + e;
                        v[e] = (j <= i) ? cf[e] * __expf(Ac[i] - Ac[j]) * dts[j] : 0.f;
                    }
                }
            }
            *(uint4*)((char*)Ms + SW128((uint32_t)(i * 128 + cu * 16))) = pack8h(v);
        }
#pragma unroll
        for (int it = 0; it < 2; ++it) {
            int u = tid + it * 256;
            int j = u >> 3, cu = u & 7;
            uint4 v = *(const uint4*)&xBCh[(size_t)(l0 + jt + j) * CONVDIM + h * HDIM + cu * 8];
            *(uint4*)((char*)Xs + SW128((uint32_t)(j * 128 + cu * 16))) = v;
        }
        __syncthreads();
#pragma unroll
        for (int ks = 0; ks < 4; ++ks) {
            uint32_t a[4][4], bf[4][2];
#pragma unroll
            for (int mt = 0; mt < 4; ++mt) {
                int row = wm + mt * 16 + (lane & 15);
                int kb  = ks * 32 + (lane >> 4) * 16;
                ldsm4(a[mt][0], a[mt][1], a[mt][2], a[mt][3],
                      sM + SW128((uint32_t)(row * 128 + kb)));
            }
#pragma unroll
            for (int nt2 = 0; nt2 < 2; ++nt2) {
                int row = ks * 16 + ((lane >> 3) & 1) * 8 + (lane & 7);
                int col = wn + nt2 * 16 + (lane >> 4) * 8;
                uint32_t r0, r1, r2, r3;
                ldsm4t(r0, r1, r2, r3, sXs + SW128((uint32_t)(row * 128 + col * 2)));
                bf[nt2 * 2][0] = r0; bf[nt2 * 2][1] = r1;
                bf[nt2 * 2 + 1][0] = r2; bf[nt2 * 2 + 1][1] = r3;
            }
#pragma unroll
            for (int mt = 0; mt < 4; ++mt)
#pragma unroll
                for (int nt = 0; nt < 4; ++nt)
                    mma16816(c[mt][nt], a[mt], bf[nt]);
        }
        __syncthreads();
    }

    const __half* pvb = prevh + (((size_t)b * NCHUNK + cc) * NHEADS + h) * (HDIM * NSTATE);
    for (int nt0 = 0; nt0 < NSTATE; nt0 += 64) {
#pragma unroll
        for (int it = 0; it < 8; ++it) {
            int u = tid + it * 256;
            int i = u >> 3, cu = u & 7;
            uint4 v = *(const uint4*)&xBCh[(size_t)(l0 + i) * CONVDIM + INTERD + NSTATE + nt0 + cu * 8];
            __half2 ea2 = __float2half2_rn(eA[i]);
            *(uint4*)((char*)Ms + SW128((uint32_t)(i * 128 + cu * 16))) = mul8h(v, ea2);
        }
#pragma unroll
        for (int it = 0; it < 2; ++it) {
            int u = tid + it * 256;
            int p = u >> 3, cu = u & 7;
            uint4 v = *(const uint4*)(pvb + (size_t)p * NSTATE + nt0 + cu * 8);
            *(uint4*)((char*)Xs + SW128((uint32_t)(p * 128 + cu * 16))) = v;
        }
        __syncthreads();
#pragma unroll
        for (int ks = 0; ks < 4; ++ks) {
            uint32_t a[4][4], bf[4][2];
#pragma unroll
            for (int mt = 0; mt < 4; ++mt) {
                int row = wm + mt * 16 + (lane & 15);
                int kb  = ks * 32 + (lane >> 4) * 16;
                ldsm4(a[mt][0], a[mt][1], a[mt][2], a[mt][3],
                      sM + SW128((uint32_t)(row * 128 + kb)));
            }
#pragma unroll
            for (int nt2 = 0; nt2 < 2; ++nt2) {
                int prow = wn + nt2 * 16 + ((lane >> 4) & 1) * 8 + (lane & 7);
                int kb   = ks * 32 + ((lane >> 3) & 1) * 16;
                uint32_t r0, r1, r2, r3;
                ldsm4(r0, r1, r2, r3, sXs + SW128((uint32_t)(prow * 128 + kb)));
                bf[nt2 * 2][0] = r0; bf[nt2 * 2][1] = r1;
                bf[nt2 * 2 + 1][0] = r2; bf[nt2 * 2 + 1][1] = r3;
            }
#pragma unroll
            for (int mt = 0; mt < 4; ++mt)
#pragma unroll
                for (int nt = 0; nt < 4; ++nt)
                    mma16816(c[mt][nt], a[mt], bf[nt]);
        }
        __syncthreads();
    }

    float Dh = Dp[h];
#pragma unroll
    for (int mt = 0; mt < 4; ++mt) {
        int i0 = wm + mt * 16 + (lane >> 2);
#pragma unroll
        for (int nt = 0; nt < 4; ++nt) {
            int p = wn + nt * 8 + (lane & 3) * 2;
#pragma unroll
            for (int half = 0; half < 2; ++half) {
                int i = i0 + half * 8;
                __half2 xh = *(const __half2*)&xBCh[(size_t)(l0 + i) * CONVDIM + h * HDIM + p];
                float2 xv = __half22float2(xh);
                store2(&Yh[(size_t)(l0 + i) * INTERD + h * HDIM + p],
                       c[mt][nt][half * 2 + 0] + Dh * xv.x,
                       c[mt][nt][half * 2 + 1] + Dh * xv.y);
            }
        }
    }
}

// ---------------- gate (silu, fp16 in) + RMSNorm -> fp16 Y2 ----------------
__global__ void gate_rms_kernel(const __half* __restrict__ projh,
                                const float* __restrict__ norm_w,
                                const __half* __restrict__ Yh,
                                __half* __restrict__ Y2)
{
    int row = blockIdx.x, tid = threadIdx.x;
    const __half* gr = projh + (size_t)row * PROJDIM;
    const __half* yr = Yh + (size_t)row * INTERD;
    float yv[16];
    float ss = 0.f;
#pragma unroll
    for (int t = 0; t < 16; ++t) {
        int e = tid + t * 256;
        float g = __half2float(gr[e]);
        float v = __half2float(yr[e]) * (g / (1.f + __expf(-g)));
        yv[t] = v;
        ss += v * v;
    }
    __shared__ float red[8];
#pragma unroll
    for (int o = 16; o > 0; o >>= 1) ss += __shfl_xor_sync(0xffffffff, ss, o);
    if ((tid & 31) == 0) red[tid >> 5] = ss;
    __syncthreads();
    float tot = 0.f;
#pragma unroll
    for (int w = 0; w < 8; ++w) tot += red[w];
    float scale = rsqrtf(tot / (float)INTERD + EPSV);
    __half* y2r = Y2 + (size_t)row * INTERD;
#pragma unroll
    for (int t = 0; t < 16; ++t) {
        int e = tid + t * 256;
        y2r[e] = __float2half(yv[t] * scale * norm_w[e]);
    }
}

// ---------------- launch (single stream, graph-capture safe) ----------------
extern "C" void kernel_launch(void* const* d_in, const int* in_sizes, int n_in,
                              void* d_out, int out_size)
{
    const float* hs      = (const float*)d_in[0];
    const float* W_in    = (const float*)d_in[1];
    const float* conv_w  = (const float*)d_in[2];
    const float* conv_b  = (const float*)d_in[3];
    const float* dt_bias = (const float*)d_in[4];
    const float* A_log   = (const float*)d_in[5];
    const float* Dp      = (const float*)d_in[6];
    const float* norm_w  = (const float*)d_in[7];
    const float* W_out   = (const float*)d_in[8];
    float* out = (float*)d_out;

    float *dtv, *Acum;
    __half *projh, *xBCh, *CBh, *statesh, *prevh, *Yh, *A2, *Win2, *Y2, *Wout2;
    cudaGetSymbolAddress((void**)&projh,   g_projh);
    cudaGetSymbolAddress((void**)&xBCh,    g_xBCh);
    cudaGetSymbolAddress((void**)&dtv,     g_dtv);
    cudaGetSymbolAddress((void**)&Acum,    g_Acum);
    cudaGetSymbolAddress((void**)&CBh,     g_CBh);
    cudaGetSymbolAddress((void**)&statesh, g_statesh);
    cudaGetSymbolAddress((void**)&prevh,   g_prevh);
    cudaGetSymbolAddress((void**)&Yh,      g_Yh);
    cudaGetSymbolAddress((void**)&A2,      g_A2);
    cudaGetSymbolAddress((void**)&Win2,    g_Win2);
    cudaGetSymbolAddress((void**)&Y2,      g_Y2);
    cudaGetSymbolAddress((void**)&Wout2,   g_Wout2);

    cudaFuncSetAttribute(gemm_fp16_mma<__half>,
                         cudaFuncAttributeMaxDynamicSharedMemorySize, TSMEM);
    cudaFuncSetAttribute(gemm_fp16_mma<float>,
                         cudaFuncAttributeMaxDynamicSharedMemorySize, TSMEM);
    cudaFuncSetAttribute(states_mma,
                         cudaFuncAttributeMaxDynamicSharedMemorySize, SSM_SMEM);
    cudaFuncSetAttribute(cb_mma,
                         cudaFuncAttributeMaxDynamicSharedMemorySize, CB_SMEM);

    // 0) fused fp32 -> fp16 conversion (hs, W_in, W_out)
    {
        long long tot = CVT_T1 + CVT_T2 + CVT_T3;
        cvt_all_kernel<<<(unsigned)((tot + 255) / 256), 256>>>(
            hs, W_in, W_out, A2, Win2, Wout2);
    }

    // 1) proj = hs @ W_in^T  (fp16 output)
    gemm_fp16_mma<__half><<<dim3(BL / 128, (PROJDIM + 127) / 128), 256, TSMEM>>>(
        A2, Win2, projh, BL, PROJDIM, DMODEL, PROJDIM);

    // 2) conv + silu -> fp16 xBC
    {
        int total = (BL / 4) * (CONVDIM / 2);
        conv_silu_kernel<<<(total + 255) / 256, 256>>>(projh, conv_w, conv_b, xBCh);
    }

    // 3) softplus(dt) + cumsum (warp-shuffle scan)
    dt_acum_kernel<<<dim3(NCHUNK, NHEADS, BATCH), CSIZE>>>(projh, dt_bias, A_log, dtv, Acum);

    // 4) CB = C . B^T via fp16 mma -> fp16
    cb_mma<<<dim3(2, 2, BATCH * NCHUNK), 256, CB_SMEM>>>(xBCh, CBh);

    // 5) states via mma -> fp16
    states_mma<<<dim3(NCHUNK, NHEADS, BATCH), 128, SSM_SMEM>>>(xBCh, dtv, Acum, statesh);

    // 6) scan -> fp16 prev
    scan_kernel<<<dim3(NHEADS, BATCH), 256>>>(statesh, Acum, prevh);

    // 7) Y via mma (Ydiag + Yoff + D*x) -> fp16
    y_mma<<<dim3(NCHUNK, NHEADS, BATCH), 256>>>(xBCh, dtv, Acum, CBh, prevh, Dp, Yh);

    // 8) gate + RMSNorm -> fp16
    gate_rms_kernel<<<BL, 256>>>(projh, norm_w, Yh, Y2);

    // 9) out = Y @ W_out^T (fp32 output)
    gemm_fp16_mma<float><<<dim3(BL / 128, DMODEL / 128), 256, TSMEM>>>(
        Y2, Wout2, out, BL, DMODEL, INTERD, DMODEL);
}

// round 16
// speedup vs baseline: 1.1391x; 1.0207x over previous
#include <cuda_runtime.h>
#include <cuda_fp16.h>
#include <cstdint>

// ---------------- problem constants ----------------
#define BATCH    2
#define LSEQ     2048
#define DMODEL   2048
#define INTERD   4096
#define NHEADS   64
#define HDIM     64
#define NSTATE   128
#define KCONV    4
#define CSIZE    256
#define NCHUNK   (LSEQ / CSIZE)                 // 8
#define CONVDIM  (INTERD + 2 * NSTATE)          // 4352
#define PROJDIM  (INTERD + CONVDIM + NHEADS)    // 8512
#define BL       (BATCH * LSEQ)                 // 4096
#define EPSV     1e-5f

// ---------------- device scratch (static; no allocs allowed) ----------------
__device__ __half g_projh [(size_t)BL * PROJDIM];
__device__ __half g_xBCh  [(size_t)BL * CONVDIM];
__device__ float g_dtv    [(size_t)BL * NHEADS];
__device__ float g_Acum   [(size_t)BATCH * NHEADS * NCHUNK * CSIZE];
__device__ __half g_CBh   [(size_t)BATCH * NCHUNK * CSIZE * CSIZE];
__device__ __half g_statesh[(size_t)BATCH * NCHUNK * NHEADS * HDIM * NSTATE];
__device__ __half g_prevh [(size_t)BATCH * NCHUNK * NHEADS * HDIM * NSTATE];
__device__ __half g_Yh    [(size_t)BL * INTERD];
__device__ __half g_A2    [(size_t)BL * DMODEL];
__device__ __half g_Win2  [(size_t)PROJDIM * DMODEL];
__device__ __half g_Y2    [(size_t)BL * INTERD];
__device__ __half g_Wout2 [(size_t)DMODEL * INTERD];

// =====================================================================
// common mma helpers
// =====================================================================
__device__ __forceinline__ uint32_t smem_u32(const void* p) {
    return (uint32_t)__cvta_generic_to_shared(p);
}
#define SW128(o) ((o) ^ (((o) >> 3) & 0x70))
#define SW256(o) ((o) ^ (((o) >> 4) & 0x70))

__device__ __forceinline__ void cp_async16(uint32_t d, const void* g, int sz) {
    asm volatile("cp.async.cg.shared.global [%0], [%1], 16, %2;"
                 :: "r"(d), "l"(g), "r"(sz) : "memory");
}
#define CP_COMMIT() asm volatile("cp.async.commit_group;" ::: "memory")
#define CP_WAIT1()  asm volatile("cp.async.wait_group 1;" ::: "memory")

__device__ __forceinline__ void ldsm4(uint32_t& r0, uint32_t& r1, uint32_t& r2,
                                      uint32_t& r3, uint32_t a) {
    asm volatile("ldmatrix.sync.aligned.m8n8.x4.shared.b16 {%0,%1,%2,%3}, [%4];"
                 : "=r"(r0), "=r"(r1), "=r"(r2), "=r"(r3) : "r"(a));
}
__device__ __forceinline__ void ldsm4t(uint32_t& r0, uint32_t& r1, uint32_t& r2,
                                       uint32_t& r3, uint32_t a) {
    asm volatile("ldmatrix.sync.aligned.m8n8.x4.trans.shared.b16 {%0,%1,%2,%3}, [%4];"
                 : "=r"(r0), "=r"(r1), "=r"(r2), "=r"(r3) : "r"(a));
}
__device__ __forceinline__ void mma16816(float* c, const uint32_t* a, const uint32_t* b) {
    asm volatile(
        "mma.sync.aligned.m16n8k16.row.col.f32.f16.f16.f32 "
        "{%0,%1,%2,%3}, {%4,%5,%6,%7}, {%8,%9}, {%0,%1,%2,%3};"
        : "+f"(c[0]), "+f"(c[1]), "+f"(c[2]), "+f"(c[3])
        : "r"(a[0]), "r"(a[1]), "r"(a[2]), "r"(a[3]), "r"(b[0]), "r"(b[1]));
}

__device__ __forceinline__ uint4 pack8h(const float* v) {
    __half h[8];
#pragma unroll
    for (int e = 0; e < 8; ++e) h[e] = __float2half(v[e]);
    uint4 r;
    r.x = ((uint32_t)*(uint16_t*)&h[1] << 16) | *(uint16_t*)&h[0];
    r.y = ((uint32_t)*(uint16_t*)&h[3] << 16) | *(uint16_t*)&h[2];
    r.z = ((uint32_t)*(uint16_t*)&h[5] << 16) | *(uint16_t*)&h[4];
    r.w = ((uint32_t)*(uint16_t*)&h[7] << 16) | *(uint16_t*)&h[6];
    return r;
}
__device__ __forceinline__ uint4 mul8h(uint4 v, __half2 w) {
    __half2* p = (__half2*)&v;
    p[0] = __hmul2(p[0], w); p[1] = __hmul2(p[1], w);
    p[2] = __hmul2(p[2], w); p[3] = __hmul2(p[3], w);
    return v;
}

__device__ __forceinline__ void store2(float* p, float a, float b) {
    *(float2*)p = make_float2(a, b);
}
__device__ __forceinline__ void store2(__half* p, float a, float b) {
    __half2 h; h.x = __float2half(a); h.y = __float2half(b);
    *(__half2*)p = h;
}

// =====================================================================
// big fp16 GEMM: BM=BN=128, BK=64, 3 stages, 256 threads, 2 CTAs/SM
// =====================================================================
#define TSTAGE_B (128 * 128 * 2)             // 32768
#define TNSTG    3
#define TSMEM    (TNSTG * TSTAGE_B)          // 98304

template <typename TOUT>
__global__ void __launch_bounds__(256, 2) gemm_fp16_mma(
    const __half* __restrict__ A, const __half* __restrict__ Bm,
    TOUT* __restrict__ C, int M, int N, int K, int ldc)
{
    extern __shared__ __align__(1024) char smem[];
    const uint32_t sbase = smem_u32(smem);
    const int tid  = threadIdx.x;
    const int wid  = tid >> 5, lane = tid & 31;
    const int bm   = blockIdx.x * 128, bn = blockIdx.y * 128;
    const int wm   = (wid & 1) * 64;
    const int wn   = (wid >> 1) * 32;
    const int KT   = K >> 6;

    float c[4][4][4];
#pragma unroll
    for (int mt = 0; mt < 4; ++mt)
#pragma unroll
        for (int nt = 0; nt < 4; ++nt)
#pragma unroll
            for (int q = 0; q < 4; ++q) c[mt][nt][q] = 0.f;

#define LOAD_STAGE(kt, s) do {                                               \
    uint32_t st_ = sbase + (s) * TSTAGE_B;                                   \
    _Pragma("unroll")                                                        \
    for (int i_ = 0; i_ < 4; ++i_) {                                         \
        int u_ = tid + i_ * 256;                                             \
        int r_ = u_ >> 3, lu_ = u_ & 7;                                      \
        uint32_t d_ = st_ + SW128((uint32_t)(r_ * 128 + lu_ * 16));          \
        const void* g_ = (const char*)A +                                    \
            (((size_t)(bm + r_) * K + (size_t)(kt) * 64 + lu_ * 8) << 1);    \
        cp_async16(d_, g_, 16);                                              \
    }                                                                        \
    _Pragma("unroll")                                                        \
    for (int i_ = 0; i_ < 4; ++i_) {                                         \
        int u_ = tid + i_ * 256;                                             \
        int r_ = u_ >> 3, lu_ = u_ & 7;                                      \
        int gn_ = bn + r_;                                                   \
        uint32_t d_ = st_ + 16384 + SW128((uint32_t)(r_ * 128 + lu_ * 16));  \
        const void* g_ = (const char*)Bm +                                   \
            (((size_t)gn_ * K + (size_t)(kt) * 64 + lu_ * 8) << 1);          \
        cp_async16(d_, g_, gn_ < N ? 16 : 0);                                \
    }                                                                        \
} while (0)

    LOAD_STAGE(0, 0); CP_COMMIT();
    LOAD_STAGE(1, 1); CP_COMMIT();

    const int a_row = (lane & 15);
    const int a_ku  = (lane >> 4) * 16;
    const int b_row = ((lane >> 4) & 1) * 8 + (lane & 7);
    const int b_ku  = ((lane >> 3) & 1) * 16;

    for (int kt = 0; kt < KT; ++kt) {
        const int s = kt % 3;
        CP_WAIT1();
        __syncthreads();
        if (kt + 2 < KT) LOAD_STAGE(kt + 2, (kt + 2) % 3);
        CP_COMMIT();

        const uint32_t stA = sbase + s * TSTAGE_B;
        const uint32_t stB = stA + 16384;
#pragma unroll
        for (int ks = 0; ks < 4; ++ks) {
            uint32_t a[4][4], b[4][2];
#pragma unroll
            for (int mt = 0; mt < 4; ++mt) {
                uint32_t off = (uint32_t)((wm + mt * 16 + a_row) * 128 + ks * 32 + a_ku);
                ldsm4(a[mt][0], a[mt][1], a[mt][2], a[mt][3], stA + SW128(off));
            }
#pragma unroll
            for (int pr = 0; pr < 2; ++pr) {
                uint32_t off = (uint32_t)((wn + pr * 16 + b_row) * 128 + ks * 32 + b_ku);
                uint32_t r0, r1, r2, r3;
                ldsm4(r0, r1, r2, r3, stB + SW128(off));
                b[pr * 2][0] = r0; b[pr * 2][1] = r1;
                b[pr * 2 + 1][0] = r2; b[pr * 2 + 1][1] = r3;
            }
#pragma unroll
            for (int mt = 0; mt < 4; ++mt)
#pragma unroll
                for (int nt = 0; nt < 4; ++nt)
                    mma16816(c[mt][nt], a[mt], b[nt]);
        }
    }

#pragma unroll
    for (int mt = 0; mt < 4; ++mt) {
        int r0 = bm + wm + mt * 16 + (lane >> 2);
#pragma unroll
        for (int nt = 0; nt < 4; ++nt) {
            int col = bn + wn + nt * 8 + (lane & 3) * 2;
            if (col < N) {
                store2(&C[(size_t)r0 * ldc + col], c[mt][nt][0], c[mt][nt][1]);
                store2(&C[(size_t)(r0 + 8) * ldc + col], c[mt][nt][2], c[mt][nt][3]);
            }
        }
    }
}

// ---------------- fused fp32 -> fp16 convert of hs, W_in, W_out ----------------
#define CVT_T1 ((long long)BL * DMODEL / 4)
#define CVT_T2 ((long long)PROJDIM * DMODEL / 4)
#define CVT_T3 ((long long)DMODEL * INTERD / 4)
__global__ void cvt_all_kernel(const float* __restrict__ hs,
                               const float* __restrict__ W_in,
                               const float* __restrict__ W_out,
                               __half* __restrict__ A2,
                               __half* __restrict__ Win2,
                               __half* __restrict__ Wout2)
{
    long long t = (long long)blockIdx.x * blockDim.x + threadIdx.x;
    const float* src; __half* dst; long long o;
    if (t < CVT_T1) { src = hs; dst = A2; o = t; }
    else if (t < CVT_T1 + CVT_T2) { src = W_in; dst = Win2; o = t - CVT_T1; }
    else if (t < CVT_T1 + CVT_T2 + CVT_T3) { src = W_out; dst = Wout2; o = t - CVT_T1 - CVT_T2; }
    else return;
    float4 a = *(const float4*)(src + o * 4);
    __half h[4];
    h[0] = __float2half(a.x); h[1] = __float2half(a.y);
    h[2] = __float2half(a.z); h[3] = __float2half(a.w);
    uint2 r;
    r.x = ((uint32_t)*(uint16_t*)&h[1] << 16) | *(uint16_t*)&h[0];
    r.y = ((uint32_t)*(uint16_t*)&h[3] << 16) | *(uint16_t*)&h[2];
    *(uint2*)(dst + o * 4) = r;
}

// ---------------- depthwise causal conv (K=4) + bias + silu ----------------
// sliding window: 2 channels x 4 consecutive timesteps per thread
__global__ void conv_silu_kernel(const __half* __restrict__ projh,
                                 const float* __restrict__ cw,
                                 const float* __restrict__ cb,
                                 __half* __restrict__ xBCh)
{
    const int NG = CONVDIM / 2;
    int idx = blockIdx.x * blockDim.x + threadIdx.x;
    if (idx >= (BL / 4) * NG) return;
    int g   = idx % NG;
    int r4  = idx / NG;
    int bl0 = r4 * 4;
    int l0  = bl0 % LSEQ;
    int ch  = g * 2;

    float4 w0 = *(const float4*)&cw[ch * 4];
    float4 w1 = *(const float4*)&cw[(ch + 1) * 4];
    float wa0[4] = {w0.x, w0.y, w0.z, w0.w};
    float wa1[4] = {w1.x, w1.y, w1.z, w1.w};
    float b0 = cb[ch], b1 = cb[ch + 1];

    float2 xv[7];
#pragma unroll
    for (int t = 0; t < 7; ++t) {
        int l = l0 + t - 3;
        if (l >= 0) {
            __half2 h = *(const __half2*)(projh +
                (size_t)(bl0 + t - 3) * PROJDIM + INTERD + ch);
            xv[t] = __half22float2(h);
        } else {
            xv[t] = make_float2(0.f, 0.f);
        }
    }
#pragma unroll
    for (int q = 0; q < 4; ++q) {
        float a0 = b0, a1 = b1;
#pragma unroll
        for (int k = 0; k < 4; ++k) {
            a0 += wa0[k] * xv[q + k].x;
            a1 += wa1[k] * xv[q + k].y;
        }
        float o0 = a0 / (1.f + __expf(-a0));
        float o1 = a1 / (1.f + __expf(-a1));
        __half2 ov; ov.x = __float2half(o0); ov.y = __float2half(o1);
        *(__half2*)(xBCh + (size_t)(bl0 + q) * CONVDIM + ch) = ov;
    }
}

// ---------------- softplus(dt+bias), per-chunk inclusive cumsum (warp scan) ----------------
__global__ void dt_acum_kernel(const __half* __restrict__ projh,
                               const float* __restrict__ dt_bias,
                               const float* __restrict__ A_log,
                               float* __restrict__ dtv,
                               float* __restrict__ Acum)
{
    int cc = blockIdx.x, h = blockIdx.y, b = blockIdx.z;
    int i  = threadIdx.x;
    int wid = i >> 5, lane = i & 31;
    int l  = cc * CSIZE + i;
    float d  = __half2float(projh[(size_t)(b * LSEQ + l) * PROJDIM + INTERD + CONVDIM + h])
             + dt_bias[h];
    float sp = (d > 20.f) ? d : log1pf(expf(d));
    dtv[(size_t)(b * LSEQ + l) * NHEADS + h] = sp;
    float v = sp * (-expf(A_log[h]));
#pragma unroll
    for (int o = 1; o < 32; o <<= 1) {
        float t = __shfl_up_sync(0xffffffff, v, o);
        if (lane >= o) v += t;
    }
    __shared__ float wsum[8], wpre[8];
    if (lane == 31) wsum[wid] = v;
    __syncthreads();
    if (i < 8) {
        float s = wsum[i];
#pragma unroll
        for (int o = 1; o < 8; o <<= 1) {
            float t = __shfl_up_sync(0xff, s, o);
            if (i >= o) s += t;
        }
        wpre[i] = s - wsum[i];
    }
    __syncthreads();
    Acum[(((size_t)b * NHEADS + h) * NCHUNK + cc) * CSIZE + i] = v + wpre[wid];
}

// =====================================================================
// CB via fp16 mma -> fp16 output
// =====================================================================
#define CB_SMEM (2 * 128 * 256)   // 65536 B
__global__ void __launch_bounds__(256) cb_mma(
    const __half* __restrict__ xBCh, __half* __restrict__ CBh)
{
    extern __shared__ __align__(1024) char sm[];
    __half* Cs = (__half*)sm;
    __half* Bs = (__half*)(sm + 32768);
    const uint32_t sC = smem_u32(Cs), sB = smem_u32(Bs);

    const int bj = blockIdx.x * 128, bi = blockIdx.y * 128;
    const int bc = blockIdx.z;
    const int b = bc / NCHUNK, cc = bc % NCHUNK;
    const int l0 = b * LSEQ + cc * CSIZE;
    const int tid = threadIdx.x, wid = tid >> 5, lane = tid & 31;
    const int wm = (wid & 1) * 64;
    const int wn = (wid >> 1) * 32;

#pragma unroll
    for (int it = 0; it < 8; ++it) {
        int u = tid + it * 256;
        int r = u >> 4, cu = u & 15;
        uint4 vc = *(const uint4*)&xBCh[(size_t)(l0 + bi + r) * CONVDIM + INTERD + NSTATE + cu * 8];
        uint4 vb = *(const uint4*)&xBCh[(size_t)(l0 + bj + r) * CONVDIM + INTERD + cu * 8];
        *(uint4*)((char*)Cs + SW256((uint32_t)(r * 256 + cu * 16))) = vc;
        *(uint4*)((char*)Bs + SW256((uint32_t)(r * 256 + cu * 16))) = vb;
    }
    __syncthreads();

    float c[4][4][4];
#pragma unroll
    for (int mt = 0; mt < 4; ++mt)
#pragma unroll
        for (int nt = 0; nt < 4; ++nt)
#pragma unroll
            for (int q = 0; q < 4; ++q) c[mt][nt][q] = 0.f;

    const int a_row = (lane & 15);
    const int a_ku  = (lane >> 4) * 16;
    const int b_row = ((lane >> 4) & 1) * 8 + (lane & 7);
    const int b_ku  = ((lane >> 3) & 1) * 16;

#pragma unroll
    for (int ks = 0; ks < 8; ++ks) {
        uint32_t a[4][4], bf[4][2];
#pragma unroll
        for (int mt = 0; mt < 4; ++mt) {
            uint32_t off = (uint32_t)((wm + mt * 16 + a_row) * 256 + ks * 32 + a_ku);
            ldsm4(a[mt][0], a[mt][1], a[mt][2], a[mt][3], sC + SW256(off));
        }
#pragma unroll
        for (int pr = 0; pr < 2; ++pr) {
            uint32_t off = (uint32_t)((wn + pr * 16 + b_row) * 256 + ks * 32 + b_ku);
            uint32_t r0, r1, r2, r3;
            ldsm4(r0, r1, r2, r3, sB + SW256(off));
            bf[pr * 2][0] = r0; bf[pr * 2][1] = r1;
            bf[pr * 2 + 1][0] = r2; bf[pr * 2 + 1][1] = r3;
        }
#pragma unroll
        for (int mt = 0; mt < 4; ++mt)
#pragma unroll
            for (int nt = 0; nt < 4; ++nt)
                mma16816(c[mt][nt], a[mt], bf[nt]);
    }

    __half* cbo = CBh + (size_t)bc * CSIZE * CSIZE;
#pragma unroll
    for (int mt = 0; mt < 4; ++mt) {
        int gi = bi + wm + mt * 16 + (lane >> 2);
#pragma unroll
        for (int nt = 0; nt < 4; ++nt) {
            int gj = bj + wn + nt * 8 + (lane & 3) * 2;
            store2(&cbo[(size_t)gi * CSIZE + gj], c[mt][nt][0], c[mt][nt][1]);
            store2(&cbo[(size_t)(gi + 8) * CSIZE + gj], c[mt][nt][2], c[mt][nt][3]);
        }
    }
}

// =====================================================================
// states via mma -> fp16 output
// =====================================================================
#define SSM_SMEM (16384 + 32768 + 512)
__global__ void __launch_bounds__(128) states_mma(
    const __half* __restrict__ xBCh, const float* __restrict__ dtv,
    const float* __restrict__ Acum, __half* __restrict__ statesh)
{
    extern __shared__ __align__(1024) char sm[];
    __half* Xw = (__half*)sm;
    __half* Bs = (__half*)(sm + 16384);
    float*  wv = (float*)(sm + 49152);
    const uint32_t sX = smem_u32(Xw), sB = smem_u32(Bs);

    const int cc = blockIdx.x, h = blockIdx.y, b = blockIdx.z;
    const int tid = threadIdx.x, wid = tid >> 5, lane = tid & 31;
    const float* Ab = Acum + (((size_t)b * NHEADS + h) * NCHUNK + cc) * CSIZE;
    const float AcLast = Ab[CSIZE - 1];
    const int l0 = b * LSEQ + cc * CSIZE;

    float c[4][4][4];
#pragma unroll
    for (int mt = 0; mt < 4; ++mt)
#pragma unroll
        for (int nt = 0; nt < 4; ++nt)
#pragma unroll
            for (int q = 0; q < 4; ++q) c[mt][nt][q] = 0.f;

    for (int jt = 0; jt < CSIZE; jt += 128) {
        wv[tid] = __expf(AcLast - Ab[jt + tid]) * dtv[(size_t)(l0 + jt + tid) * NHEADS + h];
        __syncthreads();
#pragma unroll
        for (int it = 0; it < 8; ++it) {
            int u = tid + it * 128;
            int j = u >> 3, cu = u & 7;
            uint4 v = *(const uint4*)&xBCh[(size_t)(l0 + jt + j) * CONVDIM + h * HDIM + cu * 8];
            __half2 w2 = __float2half2_rn(wv[j]);
            *(uint4*)((char*)Xw + SW128((uint32_t)(j * 128 + cu * 16))) = mul8h(v, w2);
        }
#pragma unroll
        for (int it = 0; it < 16; ++it) {
            int u = tid + it * 128;
            int j = u >> 4, cu = u & 15;
            uint4 v = *(const uint4*)&xBCh[(size_t)(l0 + jt + j) * CONVDIM + INTERD + cu * 8];
            *(uint4*)((char*)Bs + SW256((uint32_t)(j * 256 + cu * 16))) = v;
        }
        __syncthreads();
#pragma unroll
        for (int ks = 0; ks < 8; ++ks) {
            uint32_t a[4][4], bf[4][2];
#pragma unroll
            for (int mt = 0; mt < 4; ++mt) {
                int row = ks * 16 + ((lane >> 4) & 1) * 8 + (lane & 7);
                int col = mt * 16 + ((lane >> 3) & 1) * 8;
                ldsm4t(a[mt][0], a[mt][1], a[mt][2], a[mt][3],
                       sX + SW128((uint32_t)(row * 128 + col * 2)));
            }
#pragma unroll
            for (int nt2 = 0; nt2 < 2; ++nt2) {
                int row = ks * 16 + ((lane >> 3) & 1) * 8 + (lane & 7);
                int col = wid * 32 + nt2 * 16 + (lane >> 4) * 8;
                uint32_t r0, r1, r2, r3;
                ldsm4t(r0, r1, r2, r3, sB + SW256((uint32_t)(row * 256 + col * 2)));
                bf[nt2 * 2][0] = r0; bf[nt2 * 2][1] = r1;
                bf[nt2 * 2 + 1][0] = r2; bf[nt2 * 2 + 1][1] = r3;
            }
#pragma unroll
            for (int mt = 0; mt < 4; ++mt)
#pragma unroll
                for (int nt = 0; nt < 4; ++nt)
                    mma16816(c[mt][nt], a[mt], bf[nt]);
        }
        __syncthreads();
    }
    __half* so = statesh + (((size_t)b * NCHUNK + cc) * NHEADS + h) * (HDIM * NSTATE);
#pragma unroll
    for (int mt = 0; mt < 4; ++mt) {
        int p0 = mt * 16 + (lane >> 2);
#pragma unroll
        for (int nt = 0; nt < 4; ++nt) {
            int n = wid * 32 + nt * 8 + (lane & 3) * 2;
            store2(&so[p0 * NSTATE + n], c[mt][nt][0], c[mt][nt][1]);
            store2(&so[(p0 + 8) * NSTATE + n], c[mt][nt][2], c[mt][nt][3]);
        }
    }
}

// ---------------- inter-chunk recurrence (parallelized over elements) ----------------
// grid (4, NHEADS, BATCH), 256 threads; each thread carries 4 half2 lanes.
__global__ void scan_kernel(const __half* __restrict__ statesh,
                            const float* __restrict__ Acum,
                            __half* __restrict__ prevh)
{
    int seg = blockIdx.x;               // 0..3 segments of 1024 half2
    int h = blockIdx.y, b = blockIdx.z;
    int tid = threadIdx.x;
    int e2 = seg * 1024 + tid;          // half2 index base (stride 256, 4 iters)
    float2 carry[4];
#pragma unroll
    for (int t = 0; t < 4; ++t) carry[t] = make_float2(0.f, 0.f);
    for (int cc = 0; cc < NCHUNK; ++cc) {
        float cd = expf(Acum[(((size_t)b * NHEADS + h) * NCHUNK + cc) * CSIZE + CSIZE - 1]);
        size_t base2 = ((((size_t)b * NCHUNK + cc) * NHEADS + h) * (HDIM * NSTATE)) >> 1;
#pragma unroll
        for (int t = 0; t < 4; ++t) {
            size_t idx = base2 + e2 + t * 256;
            float2 sf = __half22float2(((const __half2*)statesh)[idx]);
            __half2 pv; pv.x = __float2half(carry[t].x); pv.y = __float2half(carry[t].y);
            ((__half2*)prevh)[idx] = pv;
            carry[t].x = cd * carry[t].x + sf.x;
            carry[t].y = cd * carry[t].y + sf.y;
        }
    }
}

// =====================================================================
// Y via mma: Y[i,p] = M @ X + Ce @ prev^T + D*x  (fp16 output)
// =====================================================================
__global__ void __launch_bounds__(256) y_mma(
    const __half* __restrict__ xBCh, const float* __restrict__ dtv,
    const float* __restrict__ Acum, const __half* __restrict__ CBh,
    const __half* __restrict__ prevh, const float* __restrict__ Dp,
    __half* __restrict__ Yh)
{
    __shared__ float Ac[CSIZE], dts[CSIZE], rowf[CSIZE], eA[CSIZE], colf[64];
    __shared__ __align__(1024) __half Ms[CSIZE * 64];
    __shared__ __align__(1024) __half Xs[64 * 64];
    const uint32_t sM = smem_u32(Ms), sXs = smem_u32(Xs);

    const int cc = blockIdx.x, h = blockIdx.y, b = blockIdx.z;
    const int tid = threadIdx.x, wid = tid >> 5, lane = tid & 31;
    const int wm = (wid & 3) * 64;
    const int wn = (wid >> 2) * 32;
    const int l0 = b * LSEQ + cc * CSIZE;

    Ac[tid]  = Acum[(((size_t)b * NHEADS + h) * NCHUNK + cc) * CSIZE + tid];
    dts[tid] = dtv[(size_t)(l0 + tid) * NHEADS + h];
    __syncthreads();
    eA[tid] = __expf(Ac[tid]);

    const __half* CBb = CBh + ((size_t)b * NCHUNK + cc) * CSIZE * CSIZE;

    float c[4][4][4];
#pragma unroll
    for (int mt = 0; mt < 4; ++mt)
#pragma unroll
        for (int nt = 0; nt < 4; ++nt)
#pragma unroll
            for (int q = 0; q < 4; ++q) c[mt][nt][q] = 0.f;

    for (int jt = 0; jt < CSIZE; jt += 64) {
        float A_ref = Ac[jt + 63];
        if (tid < 64) colf[tid] = __expf(A_ref - Ac[jt + tid]) * dts[jt + tid];
        rowf[tid] = __expf(Ac[tid] - A_ref);
        __syncthreads();
#pragma unroll
        for (int it = 0; it < 8; ++it) {
            int u = tid + it * 256;
            int i = u >> 3, cu = u & 7;
            float v[8];
            if (i < jt) {
#pragma unroll
                for (int e = 0; e < 8; ++e) v[e] = 0.f;
            } else {
                uint4 cbv = *(const uint4*)&CBb[(size_t)i * CSIZE + jt + cu * 8];
                __half2* ch2 = (__half2*)&cbv;
                float cf[8];
#pragma unroll
                for (int e2 = 0; e2 < 4; ++e2) {
                    float2 f = __half22float2(ch2[e2]);
                    cf[e2 * 2] = f.x; cf[e2 * 2 + 1] = f.y;
                }
                if (i >= jt + 64) {
                    float rf = rowf[i];
#pragma unroll
                    for (int e = 0; e < 8; ++e) v[e] = cf[e] * rf * colf[cu * 8 + e];
                } else {
#pragma unroll
                    for (int e = 0; e < 8; ++e) {
                        int j = jt + cu * 8 + e;
                        v[e] = (j <= i) ? cf[e] * __expf(Ac[i] - Ac[j]) * dts[j] : 0.f;
                    }
                }
            }
            *(uint4*)((char*)Ms + SW128((uint32_t)(i * 128 + cu * 16))) = pack8h(v);
        }
#pragma unroll
        for (int it = 0; it < 2; ++it) {
            int u = tid + it * 256;
            int j = u >> 3, cu = u & 7;
            uint4 v = *(const uint4*)&xBCh[(size_t)(l0 + jt + j) * CONVDIM + h * HDIM + cu * 8];
            *(uint4*)((char*)Xs + SW128((uint32_t)(j * 128 + cu * 16))) = v;
        }
        __syncthreads();
#pragma unroll
        for (int ks = 0; ks < 4; ++ks) {
            uint32_t a[4][4], bf[4][2];
#pragma unroll
            for (int mt = 0; mt < 4; ++mt) {
                int row = wm + mt * 16 + (lane & 15);
                int kb  = ks * 32 + (lane >> 4) * 16;
                ldsm4(a[mt][0], a[mt][1], a[mt][2], a[mt][3],
                      sM + SW128((uint32_t)(row * 128 + kb)));
            }
#pragma unroll
            for (int nt2 = 0; nt2 < 2; ++nt2) {
                int row = ks * 16 + ((lane >> 3) & 1) * 8 + (lane & 7);
                int col = wn + nt2 * 16 + (lane >> 4) * 8;
                uint32_t r0, r1, r2, r3;
                ldsm4t(r0, r1, r2, r3, sXs + SW128((uint32_t)(row * 128 + col * 2)));
                bf[nt2 * 2][0] = r0; bf[nt2 * 2][1] = r1;
                bf[nt2 * 2 + 1][0] = r2; bf[nt2 * 2 + 1][1] = r3;
            }
#pragma unroll
            for (int mt = 0; mt < 4; ++mt)
#pragma unroll
                for (int nt = 0; nt < 4; ++nt)
                    mma16816(c[mt][nt], a[mt], bf[nt]);
        }
        __syncthreads();
    }

    const __half* pvb = prevh + (((size_t)b * NCHUNK + cc) * NHEADS + h) * (HDIM * NSTATE);
    for (int nt0 = 0; nt0 < NSTATE; nt0 += 64) {
#pragma unroll
        for (int it = 0; it < 8; ++it) {
            int u = tid + it * 256;
            int i = u >> 3, cu = u & 7;
            uint4 v = *(const uint4*)&xBCh[(size_t)(l0 + i) * CONVDIM + INTERD + NSTATE + nt0 + cu * 8];
            __half2 ea2 = __float2half2_rn(eA[i]);
            *(uint4*)((char*)Ms + SW128((uint32_t)(i * 128 + cu * 16))) = mul8h(v, ea2);
        }
#pragma unroll
        for (int it = 0; it < 2; ++it) {
            int u = tid + it * 256;
            int p = u >> 3, cu = u & 7;
            uint4 v = *(const uint4*)(pvb + (size_t)p * NSTATE + nt0 + cu * 8);
            *(uint4*)((char*)Xs + SW128((uint32_t)(p * 128 + cu * 16))) = v;
        }
        __syncthreads();
#pragma unroll
        for (int ks = 0; ks < 4; ++ks) {
            uint32_t a[4][4], bf[4][2];
#pragma unroll
            for (int mt = 0; mt < 4; ++mt) {
                int row = wm + mt * 16 + (lane & 15);
                int kb  = ks * 32 + (lane >> 4) * 16;
                ldsm4(a[mt][0], a[mt][1], a[mt][2], a[mt][3],
                      sM + SW128((uint32_t)(row * 128 + kb)));
            }
#pragma unroll
            for (int nt2 = 0; nt2 < 2; ++nt2) {
                int prow = wn + nt2 * 16 + ((lane >> 4) & 1) * 8 + (lane & 7);
                int kb   = ks * 32 + ((lane >> 3) & 1) * 16;
                uint32_t r0, r1, r2, r3;
                ldsm4(r0, r1, r2, r3, sXs + SW128((uint32_t)(prow * 128 + kb)));
                bf[nt2 * 2][0] = r0; bf[nt2 * 2][1] = r1;
                bf[nt2 * 2 + 1][0] = r2; bf[nt2 * 2 + 1][1] = r3;
            }
#pragma unroll
            for (int mt = 0; mt < 4; ++mt)
#pragma unroll
                for (int nt = 0; nt < 4; ++nt)
                    mma16816(c[mt][nt], a[mt], bf[nt]);
        }
        __syncthreads();
    }

    float Dh = Dp[h];
#pragma unroll
    for (int mt = 0; mt < 4; ++mt) {
        int i0 = wm + mt * 16 + (lane >> 2);
#pragma unroll
        for (int nt = 0; nt < 4; ++nt) {
            int p = wn + nt * 8 + (lane & 3) * 2;
#pragma unroll
            for (int half = 0; half < 2; ++half) {
                int i = i0 + half * 8;
                __half2 xh = *(const __half2*)&xBCh[(size_t)(l0 + i) * CONVDIM + h * HDIM + p];
                float2 xv = __half22float2(xh);
                store2(&Yh[(size_t)(l0 + i) * INTERD + h * HDIM + p],
                       c[mt][nt][half * 2 + 0] + Dh * xv.x,
                       c[mt][nt][half * 2 + 1] + Dh * xv.y);
            }
        }
    }
}

// ---------------- gate (silu, fp16 in) + RMSNorm -> fp16 Y2 ----------------
__global__ void gate_rms_kernel(const __half* __restrict__ projh,
                                const float* __restrict__ norm_w,
                                const __half* __restrict__ Yh,
                                __half* __restrict__ Y2)
{
    int row = blockIdx.x, tid = threadIdx.x;
    const __half* gr = projh + (size_t)row * PROJDIM;
    const __half* yr = Yh + (size_t)row * INTERD;
    float yv[16];
    float ss = 0.f;
#pragma unroll
    for (int t = 0; t < 16; ++t) {
        int e = tid + t * 256;
        float g = __half2float(gr[e]);
        float v = __half2float(yr[e]) * (g / (1.f + __expf(-g)));
        yv[t] = v;
        ss += v * v;
    }
    __shared__ float red[8];
#pragma unroll
    for (int o = 16; o > 0; o >>= 1) ss += __shfl_xor_sync(0xffffffff, ss, o);
    if ((tid & 31) == 0) red[tid >> 5] = ss;
    __syncthreads();
    float tot = 0.f;
#pragma unroll
    for (int w = 0; w < 8; ++w) tot += red[w];
    float scale = rsqrtf(tot / (float)INTERD + EPSV);
    __half* y2r = Y2 + (size_t)row * INTERD;
#pragma unroll
    for (int t = 0; t < 16; ++t) {
        int e = tid + t * 256;
        y2r[e] = __float2half(yv[t] * scale * norm_w[e]);
    }
}

// ---------------- launch (single stream, graph-capture safe) ----------------
extern "C" void kernel_launch(void* const* d_in, const int* in_sizes, int n_in,
                              void* d_out, int out_size)
{
    const float* hs      = (const float*)d_in[0];
    const float* W_in    = (const float*)d_in[1];
    const float* conv_w  = (const float*)d_in[2];
    const float* conv_b  = (const float*)d_in[3];
    const float* dt_bias = (const float*)d_in[4];
    const float* A_log   = (const float*)d_in[5];
    const float* Dp      = (const float*)d_in[6];
    const float* norm_w  = (const float*)d_in[7];
    const float* W_out   = (const float*)d_in[8];
    float* out = (float*)d_out;

    float *dtv, *Acum;
    __half *projh, *xBCh, *CBh, *statesh, *prevh, *Yh, *A2, *Win2, *Y2, *Wout2;
    cudaGetSymbolAddress((void**)&projh,   g_projh);
    cudaGetSymbolAddress((void**)&xBCh,    g_xBCh);
    cudaGetSymbolAddress((void**)&dtv,     g_dtv);
    cudaGetSymbolAddress((void**)&Acum,    g_Acum);
    cudaGetSymbolAddress((void**)&CBh,     g_CBh);
    cudaGetSymbolAddress((void**)&statesh, g_statesh);
    cudaGetSymbolAddress((void**)&prevh,   g_prevh);
    cudaGetSymbolAddress((void**)&Yh,      g_Yh);
    cudaGetSymbolAddress((void**)&A2,      g_A2);
    cudaGetSymbolAddress((void**)&Win2,    g_Win2);
    cudaGetSymbolAddress((void**)&Y2,      g_Y2);
    cudaGetSymbolAddress((void**)&Wout2,   g_Wout2);

    cudaFuncSetAttribute(gemm_fp16_mma<__half>,
                         cudaFuncAttributeMaxDynamicSharedMemorySize, TSMEM);
    cudaFuncSetAttribute(gemm_fp16_mma<float>,
                         cudaFuncAttributeMaxDynamicSharedMemorySize, TSMEM);
    cudaFuncSetAttribute(states_mma,
                         cudaFuncAttributeMaxDynamicSharedMemorySize, SSM_SMEM);
    cudaFuncSetAttribute(cb_mma,
                         cudaFuncAttributeMaxDynamicSharedMemorySize, CB_SMEM);

    // 0) fused fp32 -> fp16 conversion (hs, W_in, W_out)
    {
        long long tot = CVT_T1 + CVT_T2 + CVT_T3;
        cvt_all_kernel<<<(unsigned)((tot + 255) / 256), 256>>>(
            hs, W_in, W_out, A2, Win2, Wout2);
    }

    // 1) proj = hs @ W_in^T  (fp16 output)
    gemm_fp16_mma<__half><<<dim3(BL / 128, (PROJDIM + 127) / 128), 256, TSMEM>>>(
        A2, Win2, projh, BL, PROJDIM, DMODEL, PROJDIM);

    // 2) conv + silu -> fp16 xBC
    {
        int total = (BL / 4) * (CONVDIM / 2);
        conv_silu_kernel<<<(total + 255) / 256, 256>>>(projh, conv_w, conv_b, xBCh);
    }

    // 3) softplus(dt) + cumsum (warp-shuffle scan)
    dt_acum_kernel<<<dim3(NCHUNK, NHEADS, BATCH), CSIZE>>>(projh, dt_bias, A_log, dtv, Acum);

    // 4) CB = C . B^T via fp16 mma -> fp16
    cb_mma<<<dim3(2, 2, BATCH * NCHUNK), 256, CB_SMEM>>>(xBCh, CBh);

    // 5) states via mma -> fp16
    states_mma<<<dim3(NCHUNK, NHEADS, BATCH), 128, SSM_SMEM>>>(xBCh, dtv, Acum, statesh);

    // 6) scan -> fp16 prev (parallelized: 512 CTAs)
    scan_kernel<<<dim3(4, NHEADS, BATCH), 256>>>(statesh, Acum, prevh);

    // 7) Y via mma (Ydiag + Yoff + D*x) -> fp16
    y_mma<<<dim3(NCHUNK, NHEADS, BATCH), 256>>>(xBCh, dtv, Acum, CBh, prevh, Dp, Yh);

    // 8) gate + RMSNorm -> fp16
    gate_rms_kernel<<<BL, 256>>>(projh, norm_w, Yh, Y2);

    // 9) out = Y @ W_out^T (fp32 output)
    gemm_fp16_mma<float><<<dim3(BL / 128, DMODEL / 128), 256, TSMEM>>>(
        Y2, Wout2, out, BL, DMODEL, INTERD, DMODEL);
}

// round 17
// speedup vs baseline: 1.1867x; 1.0418x over previous
#include <cuda_runtime.h>
#include <cuda_fp16.h>
#include <cstdint>

// ---------------- problem constants ----------------
#define BATCH    2
#define LSEQ     2048
#define DMODEL   2048
#define INTERD   4096
#define NHEADS   64
#define HDIM     64
#define NSTATE   128
#define KCONV    4
#define CSIZE    256
#define NCHUNK   (LSEQ / CSIZE)                 // 8
#define CONVDIM  (INTERD + 2 * NSTATE)          // 4352
#define PROJDIM  (INTERD + CONVDIM + NHEADS)    // 8512
#define BL       (BATCH * LSEQ)                 // 4096
#define EPSV     1e-5f

// ---------------- device scratch (static; no allocs allowed) ----------------
__device__ __half g_projh [(size_t)BL * PROJDIM];
__device__ __half g_xBCh  [(size_t)BL * CONVDIM];
__device__ float g_dtv    [(size_t)BATCH * NHEADS * LSEQ];   // [b][h][l] layout
__device__ float g_Acum   [(size_t)BATCH * NHEADS * NCHUNK * CSIZE];
__device__ __half g_CBh   [(size_t)BATCH * NCHUNK * CSIZE * CSIZE];
__device__ __half g_statesh[(size_t)BATCH * NCHUNK * NHEADS * HDIM * NSTATE];
__device__ __half g_prevh [(size_t)BATCH * NCHUNK * NHEADS * HDIM * NSTATE];
__device__ __half g_Yh    [(size_t)BL * INTERD];
__device__ __half g_A2    [(size_t)BL * DMODEL];
__device__ __half g_Win2  [(size_t)PROJDIM * DMODEL];
__device__ __half g_Y2    [(size_t)BL * INTERD];
__device__ __half g_Wout2 [(size_t)DMODEL * INTERD];

// =====================================================================
// common mma helpers
// =====================================================================
__device__ __forceinline__ uint32_t smem_u32(const void* p) {
    return (uint32_t)__cvta_generic_to_shared(p);
}
#define SW128(o) ((o) ^ (((o) >> 3) & 0x70))
#define SW256(o) ((o) ^ (((o) >> 4) & 0x70))

__device__ __forceinline__ void cp_async16(uint32_t d, const void* g, int sz) {
    asm volatile("cp.async.cg.shared.global [%0], [%1], 16, %2;"
                 :: "r"(d), "l"(g), "r"(sz) : "memory");
}
#define CP_COMMIT() asm volatile("cp.async.commit_group;" ::: "memory")
#define CP_WAIT1()  asm volatile("cp.async.wait_group 1;" ::: "memory")

__device__ __forceinline__ void ldsm4(uint32_t& r0, uint32_t& r1, uint32_t& r2,
                                      uint32_t& r3, uint32_t a) {
    asm volatile("ldmatrix.sync.aligned.m8n8.x4.shared.b16 {%0,%1,%2,%3}, [%4];"
                 : "=r"(r0), "=r"(r1), "=r"(r2), "=r"(r3) : "r"(a));
}
__device__ __forceinline__ void ldsm4t(uint32_t& r0, uint32_t& r1, uint32_t& r2,
                                       uint32_t& r3, uint32_t a) {
    asm volatile("ldmatrix.sync.aligned.m8n8.x4.trans.shared.b16 {%0,%1,%2,%3}, [%4];"
                 : "=r"(r0), "=r"(r1), "=r"(r2), "=r"(r3) : "r"(a));
}
__device__ __forceinline__ void mma16816(float* c, const uint32_t* a, const uint32_t* b) {
    asm volatile(
        "mma.sync.aligned.m16n8k16.row.col.f32.f16.f16.f32 "
        "{%0,%1,%2,%3}, {%4,%5,%6,%7}, {%8,%9}, {%0,%1,%2,%3};"
        : "+f"(c[0]), "+f"(c[1]), "+f"(c[2]), "+f"(c[3])
        : "r"(a[0]), "r"(a[1]), "r"(a[2]), "r"(a[3]), "r"(b[0]), "r"(b[1]));
}

__device__ __forceinline__ uint4 pack8h(const float* v) {
    __half h[8];
#pragma unroll
    for (int e = 0; e < 8; ++e) h[e] = __float2half(v[e]);
    uint4 r;
    r.x = ((uint32_t)*(uint16_t*)&h[1] << 16) | *(uint16_t*)&h[0];
    r.y = ((uint32_t)*(uint16_t*)&h[3] << 16) | *(uint16_t*)&h[2];
    r.z = ((uint32_t)*(uint16_t*)&h[5] << 16) | *(uint16_t*)&h[4];
    r.w = ((uint32_t)*(uint16_t*)&h[7] << 16) | *(uint16_t*)&h[6];
    return r;
}
__device__ __forceinline__ uint4 mul8h(uint4 v, __half2 w) {
    __half2* p = (__half2*)&v;
    p[0] = __hmul2(p[0], w); p[1] = __hmul2(p[1], w);
    p[2] = __hmul2(p[2], w); p[3] = __hmul2(p[3], w);
    return v;
}

__device__ __forceinline__ void store2(float* p, float a, float b) {
    *(float2*)p = make_float2(a, b);
}
__device__ __forceinline__ void store2(__half* p, float a, float b) {
    __half2 h; h.x = __float2half(a); h.y = __float2half(b);
    *(__half2*)p = h;
}

// =====================================================================
// big fp16 GEMM: BM=BN=128, BK=64, 3 stages, 256 threads, 2 CTAs/SM
// =====================================================================
#define TSTAGE_B (128 * 128 * 2)             // 32768
#define TNSTG    3
#define TSMEM    (TNSTG * TSTAGE_B)          // 98304

template <typename TOUT>
__global__ void __launch_bounds__(256, 2) gemm_fp16_mma(
    const __half* __restrict__ A, const __half* __restrict__ Bm,
    TOUT* __restrict__ C, int M, int N, int K, int ldc)
{
    extern __shared__ __align__(1024) char smem[];
    const uint32_t sbase = smem_u32(smem);
    const int tid  = threadIdx.x;
    const int wid  = tid >> 5, lane = tid & 31;
    const int bm   = blockIdx.x * 128, bn = blockIdx.y * 128;
    const int wm   = (wid & 1) * 64;
    const int wn   = (wid >> 1) * 32;
    const int KT   = K >> 6;

    float c[4][4][4];
#pragma unroll
    for (int mt = 0; mt < 4; ++mt)
#pragma unroll
        for (int nt = 0; nt < 4; ++nt)
#pragma unroll
            for (int q = 0; q < 4; ++q) c[mt][nt][q] = 0.f;

#define LOAD_STAGE(kt, s) do {                                               \
    uint32_t st_ = sbase + (s) * TSTAGE_B;                                   \
    _Pragma("unroll")                                                        \
    for (int i_ = 0; i_ < 4; ++i_) {                                         \
        int u_ = tid + i_ * 256;                                             \
        int r_ = u_ >> 3, lu_ = u_ & 7;                                      \
        uint32_t d_ = st_ + SW128((uint32_t)(r_ * 128 + lu_ * 16));          \
        const void* g_ = (const char*)A +                                    \
            (((size_t)(bm + r_) * K + (size_t)(kt) * 64 + lu_ * 8) << 1);    \
        cp_async16(d_, g_, 16);                                              \
    }                                                                        \
    _Pragma("unroll")                                                        \
    for (int i_ = 0; i_ < 4; ++i_) {                                         \
        int u_ = tid + i_ * 256;                                             \
        int r_ = u_ >> 3, lu_ = u_ & 7;                                      \
        int gn_ = bn + r_;                                                   \
        uint32_t d_ = st_ + 16384 + SW128((uint32_t)(r_ * 128 + lu_ * 16));  \
        const void* g_ = (const char*)Bm +                                   \
            (((size_t)gn_ * K + (size_t)(kt) * 64 + lu_ * 8) << 1);          \
        cp_async16(d_, g_, gn_ < N ? 16 : 0);                                \
    }                                                                        \
} while (0)

    LOAD_STAGE(0, 0); CP_COMMIT();
    LOAD_STAGE(1, 1); CP_COMMIT();

    const int a_row = (lane & 15);
    const int a_ku  = (lane >> 4) * 16;
    const int b_row = ((lane >> 4) & 1) * 8 + (lane & 7);
    const int b_ku  = ((lane >> 3) & 1) * 16;

    for (int kt = 0; kt < KT; ++kt) {
        const int s = kt % 3;
        CP_WAIT1();
        __syncthreads();
        if (kt + 2 < KT) LOAD_STAGE(kt + 2, (kt + 2) % 3);
        CP_COMMIT();

        const uint32_t stA = sbase + s * TSTAGE_B;
        const uint32_t stB = stA + 16384;
#pragma unroll
        for (int ks = 0; ks < 4; ++ks) {
            uint32_t a[4][4], b[4][2];
#pragma unroll
            for (int mt = 0; mt < 4; ++mt) {
                uint32_t off = (uint32_t)((wm + mt * 16 + a_row) * 128 + ks * 32 + a_ku);
                ldsm4(a[mt][0], a[mt][1], a[mt][2], a[mt][3], stA + SW128(off));
            }
#pragma unroll
            for (int pr = 0; pr < 2; ++pr) {
                uint32_t off = (uint32_t)((wn + pr * 16 + b_row) * 128 + ks * 32 + b_ku);
                uint32_t r0, r1, r2, r3;
                ldsm4(r0, r1, r2, r3, stB + SW128(off));
                b[pr * 2][0] = r0; b[pr * 2][1] = r1;
                b[pr * 2 + 1][0] = r2; b[pr * 2 + 1][1] = r3;
            }
#pragma unroll
            for (int mt = 0; mt < 4; ++mt)
#pragma unroll
                for (int nt = 0; nt < 4; ++nt)
                    mma16816(c[mt][nt], a[mt], b[nt]);
        }
    }

#pragma unroll
    for (int mt = 0; mt < 4; ++mt) {
        int r0 = bm + wm + mt * 16 + (lane >> 2);
#pragma unroll
        for (int nt = 0; nt < 4; ++nt) {
            int col = bn + wn + nt * 8 + (lane & 3) * 2;
            if (col < N) {
                store2(&C[(size_t)r0 * ldc + col], c[mt][nt][0], c[mt][nt][1]);
                store2(&C[(size_t)(r0 + 8) * ldc + col], c[mt][nt][2], c[mt][nt][3]);
            }
        }
    }
}

// ---------------- fused fp32 -> fp16 convert of hs, W_in, W_out ----------------
#define CVT_T1 ((long long)BL * DMODEL / 4)
#define CVT_T2 ((long long)PROJDIM * DMODEL / 4)
#define CVT_T3 ((long long)DMODEL * INTERD / 4)
__global__ void cvt_all_kernel(const float* __restrict__ hs,
                               const float* __restrict__ W_in,
                               const float* __restrict__ W_out,
                               __half* __restrict__ A2,
                               __half* __restrict__ Win2,
                               __half* __restrict__ Wout2)
{
    long long t = (long long)blockIdx.x * blockDim.x + threadIdx.x;
    const float* src; __half* dst; long long o;
    if (t < CVT_T1) { src = hs; dst = A2; o = t; }
    else if (t < CVT_T1 + CVT_T2) { src = W_in; dst = Win2; o = t - CVT_T1; }
    else if (t < CVT_T1 + CVT_T2 + CVT_T3) { src = W_out; dst = Wout2; o = t - CVT_T1 - CVT_T2; }
    else return;
    float4 a = *(const float4*)(src + o * 4);
    __half h[4];
    h[0] = __float2half(a.x); h[1] = __float2half(a.y);
    h[2] = __float2half(a.z); h[3] = __float2half(a.w);
    uint2 r;
    r.x = ((uint32_t)*(uint16_t*)&h[1] << 16) | *(uint16_t*)&h[0];
    r.y = ((uint32_t)*(uint16_t*)&h[3] << 16) | *(uint16_t*)&h[2];
    *(uint2*)(dst + o * 4) = r;
}

// ---------------- depthwise causal conv (K=4) + bias + silu ----------------
// sliding window: 2 channels x 8 consecutive timesteps per thread
__global__ void conv_silu_kernel(const __half* __restrict__ projh,
                                 const float* __restrict__ cw,
                                 const float* __restrict__ cb,
                                 __half* __restrict__ xBCh)
{
    const int NG = CONVDIM / 2;
    int idx = blockIdx.x * blockDim.x + threadIdx.x;
    if (idx >= (BL / 8) * NG) return;
    int g   = idx % NG;
    int r8  = idx / NG;
    int bl0 = r8 * 8;                          // 8-row group (never crosses batch)
    int l0  = bl0 % LSEQ;
    int ch  = g * 2;

    float4 w0 = *(const float4*)&cw[ch * 4];
    float4 w1 = *(const float4*)&cw[(ch + 1) * 4];
    float wa0[4] = {w0.x, w0.y, w0.z, w0.w};
    float wa1[4] = {w1.x, w1.y, w1.z, w1.w};
    float b0 = cb[ch], b1 = cb[ch + 1];

    float2 xv[11];
#pragma unroll
    for (int t = 0; t < 11; ++t) {
        int l = l0 + t - 3;
        if (l >= 0) {
            __half2 h = *(const __half2*)(projh +
                (size_t)(bl0 + t - 3) * PROJDIM + INTERD + ch);
            xv[t] = __half22float2(h);
        } else {
            xv[t] = make_float2(0.f, 0.f);
        }
    }
#pragma unroll
    for (int q = 0; q < 8; ++q) {
        float a0 = b0, a1 = b1;
#pragma unroll
        for (int k = 0; k < 4; ++k) {
            a0 += wa0[k] * xv[q + k].x;
            a1 += wa1[k] * xv[q + k].y;
        }
        float o0 = a0 / (1.f + __expf(-a0));
        float o1 = a1 / (1.f + __expf(-a1));
        __half2 ov; ov.x = __float2half(o0); ov.y = __float2half(o1);
        *(__half2*)(xBCh + (size_t)(bl0 + q) * CONVDIM + ch) = ov;
    }
}

// ---------------- softplus(dt+bias), per-chunk inclusive cumsum (warp scan) ----------------
// dtv stored [b][h][l] (coalesced writes and reads)
__global__ void dt_acum_kernel(const __half* __restrict__ projh,
                               const float* __restrict__ dt_bias,
                               const float* __restrict__ A_log,
                               float* __restrict__ dtv,
                               float* __restrict__ Acum)
{
    int cc = blockIdx.x, h = blockIdx.y, b = blockIdx.z;
    int i  = threadIdx.x;
    int wid = i >> 5, lane = i & 31;
    int l  = cc * CSIZE + i;
    float d  = __half2float(projh[(size_t)(b * LSEQ + l) * PROJDIM + INTERD + CONVDIM + h])
             + dt_bias[h];
    float sp = (d > 20.f) ? d : log1pf(expf(d));
    dtv[((size_t)b * NHEADS + h) * LSEQ + l] = sp;
    float v = sp * (-expf(A_log[h]));
#pragma unroll
    for (int o = 1; o < 32; o <<= 1) {
        float t = __shfl_up_sync(0xffffffff, v, o);
        if (lane >= o) v += t;
    }
    __shared__ float wsum[8], wpre[8];
    if (lane == 31) wsum[wid] = v;
    __syncthreads();
    if (i < 8) {
        float s = wsum[i];
#pragma unroll
        for (int o = 1; o < 8; o <<= 1) {
            float t = __shfl_up_sync(0xff, s, o);
            if (i >= o) s += t;
        }
        wpre[i] = s - wsum[i];
    }
    __syncthreads();
    Acum[(((size_t)b * NHEADS + h) * NCHUNK + cc) * CSIZE + i] = v + wpre[wid];
}

// =====================================================================
// CB via fp16 mma -> fp16 output
// =====================================================================
#define CB_SMEM (2 * 128 * 256)   // 65536 B
__global__ void __launch_bounds__(256) cb_mma(
    const __half* __restrict__ xBCh, __half* __restrict__ CBh)
{
    extern __shared__ __align__(1024) char sm[];
    __half* Cs = (__half*)sm;
    __half* Bs = (__half*)(sm + 32768);
    const uint32_t sC = smem_u32(Cs), sB = smem_u32(Bs);

    const int bj = blockIdx.x * 128, bi = blockIdx.y * 128;
    const int bc = blockIdx.z;
    const int b = bc / NCHUNK, cc = bc % NCHUNK;
    const int l0 = b * LSEQ + cc * CSIZE;
    const int tid = threadIdx.x, wid = tid >> 5, lane = tid & 31;
    const int wm = (wid & 1) * 64;
    const int wn = (wid >> 1) * 32;

#pragma unroll
    for (int it = 0; it < 8; ++it) {
        int u = tid + it * 256;
        int r = u >> 4, cu = u & 15;
        uint4 vc = *(const uint4*)&xBCh[(size_t)(l0 + bi + r) * CONVDIM + INTERD + NSTATE + cu * 8];
        uint4 vb = *(const uint4*)&xBCh[(size_t)(l0 + bj + r) * CONVDIM + INTERD + cu * 8];
        *(uint4*)((char*)Cs + SW256((uint32_t)(r * 256 + cu * 16))) = vc;
        *(uint4*)((char*)Bs + SW256((uint32_t)(r * 256 + cu * 16))) = vb;
    }
    __syncthreads();

    float c[4][4][4];
#pragma unroll
    for (int mt = 0; mt < 4; ++mt)
#pragma unroll
        for (int nt = 0; nt < 4; ++nt)
#pragma unroll
            for (int q = 0; q < 4; ++q) c[mt][nt][q] = 0.f;

    const int a_row = (lane & 15);
    const int a_ku  = (lane >> 4) * 16;
    const int b_row = ((lane >> 4) & 1) * 8 + (lane & 7);
    const int b_ku  = ((lane >> 3) & 1) * 16;

#pragma unroll
    for (int ks = 0; ks < 8; ++ks) {
        uint32_t a[4][4], bf[4][2];
#pragma unroll
        for (int mt = 0; mt < 4; ++mt) {
            uint32_t off = (uint32_t)((wm + mt * 16 + a_row) * 256 + ks * 32 + a_ku);
            ldsm4(a[mt][0], a[mt][1], a[mt][2], a[mt][3], sC + SW256(off));
        }
#pragma unroll
        for (int pr = 0; pr < 2; ++pr) {
            uint32_t off = (uint32_t)((wn + pr * 16 + b_row) * 256 + ks * 32 + b_ku);
            uint32_t r0, r1, r2, r3;
            ldsm4(r0, r1, r2, r3, sB + SW256(off));
            bf[pr * 2][0] = r0; bf[pr * 2][1] = r1;
            bf[pr * 2 + 1][0] = r2; bf[pr * 2 + 1][1] = r3;
        }
#pragma unroll
        for (int mt = 0; mt < 4; ++mt)
#pragma unroll
            for (int nt = 0; nt < 4; ++nt)
                mma16816(c[mt][nt], a[mt], bf[nt]);
    }

    __half* cbo = CBh + (size_t)bc * CSIZE * CSIZE;
#pragma unroll
    for (int mt = 0; mt < 4; ++mt) {
        int gi = bi + wm + mt * 16 + (lane >> 2);
#pragma unroll
        for (int nt = 0; nt < 4; ++nt) {
            int gj = bj + wn + nt * 8 + (lane & 3) * 2;
            store2(&cbo[(size_t)gi * CSIZE + gj], c[mt][nt][0], c[mt][nt][1]);
            store2(&cbo[(size_t)(gi + 8) * CSIZE + gj], c[mt][nt][2], c[mt][nt][3]);
        }
    }
}

// =====================================================================
// states via mma -> fp16 output
// =====================================================================
#define SSM_SMEM (16384 + 32768 + 512)
__global__ void __launch_bounds__(128) states_mma(
    const __half* __restrict__ xBCh, const float* __restrict__ dtv,
    const float* __restrict__ Acum, __half* __restrict__ statesh)
{
    extern __shared__ __align__(1024) char sm[];
    __half* Xw = (__half*)sm;
    __half* Bs = (__half*)(sm + 16384);
    float*  wv = (float*)(sm + 49152);
    const uint32_t sX = smem_u32(Xw), sB = smem_u32(Bs);

    const int cc = blockIdx.x, h = blockIdx.y, b = blockIdx.z;
    const int tid = threadIdx.x, wid = tid >> 5, lane = tid & 31;
    const float* Ab = Acum + (((size_t)b * NHEADS + h) * NCHUNK + cc) * CSIZE;
    const float* dtb = dtv + ((size_t)b * NHEADS + h) * LSEQ + cc * CSIZE;
    const float AcLast = Ab[CSIZE - 1];
    const int l0 = b * LSEQ + cc * CSIZE;

    float c[4][4][4];
#pragma unroll
    for (int mt = 0; mt < 4; ++mt)
#pragma unroll
        for (int nt = 0; nt < 4; ++nt)
#pragma unroll
            for (int q = 0; q < 4; ++q) c[mt][nt][q] = 0.f;

    for (int jt = 0; jt < CSIZE; jt += 128) {
        wv[tid] = __expf(AcLast - Ab[jt + tid]) * dtb[jt + tid];
        __syncthreads();
#pragma unroll
        for (int it = 0; it < 8; ++it) {
            int u = tid + it * 128;
            int j = u >> 3, cu = u & 7;
            uint4 v = *(const uint4*)&xBCh[(size_t)(l0 + jt + j) * CONVDIM + h * HDIM + cu * 8];
            __half2 w2 = __float2half2_rn(wv[j]);
            *(uint4*)((char*)Xw + SW128((uint32_t)(j * 128 + cu * 16))) = mul8h(v, w2);
        }
#pragma unroll
        for (int it = 0; it < 16; ++it) {
            int u = tid + it * 128;
            int j = u >> 4, cu = u & 15;
            uint4 v = *(const uint4*)&xBCh[(size_t)(l0 + jt + j) * CONVDIM + INTERD + cu * 8];
            *(uint4*)((char*)Bs + SW256((uint32_t)(j * 256 + cu * 16))) = v;
        }
        __syncthreads();
#pragma unroll
        for (int ks = 0; ks < 8; ++ks) {
            uint32_t a[4][4], bf[4][2];
#pragma unroll
            for (int mt = 0; mt < 4; ++mt) {
                int row = ks * 16 + ((lane >> 4) & 1) * 8 + (lane & 7);
                int col = mt * 16 + ((lane >> 3) & 1) * 8;
                ldsm4t(a[mt][0], a[mt][1], a[mt][2], a[mt][3],
                       sX + SW128((uint32_t)(row * 128 + col * 2)));
            }
#pragma unroll
            for (int nt2 = 0; nt2 < 2; ++nt2) {
                int row = ks * 16 + ((lane >> 3) & 1) * 8 + (lane & 7);
                int col = wid * 32 + nt2 * 16 + (lane >> 4) * 8;
                uint32_t r0, r1, r2, r3;
                ldsm4t(r0, r1, r2, r3, sB + SW256((uint32_t)(row * 256 + col * 2)));
                bf[nt2 * 2][0] = r0; bf[nt2 * 2][1] = r1;
                bf[nt2 * 2 + 1][0] = r2; bf[nt2 * 2 + 1][1] = r3;
            }
#pragma unroll
            for (int mt = 0; mt < 4; ++mt)
#pragma unroll
                for (int nt = 0; nt < 4; ++nt)
                    mma16816(c[mt][nt], a[mt], bf[nt]);
        }
        __syncthreads();
    }
    __half* so = statesh + (((size_t)b * NCHUNK + cc) * NHEADS + h) * (HDIM * NSTATE);
#pragma unroll
    for (int mt = 0; mt < 4; ++mt) {
        int p0 = mt * 16 + (lane >> 2);
#pragma unroll
        for (int nt = 0; nt < 4; ++nt) {
            int n = wid * 32 + nt * 8 + (lane & 3) * 2;
            store2(&so[p0 * NSTATE + n], c[mt][nt][0], c[mt][nt][1]);
            store2(&so[(p0 + 8) * NSTATE + n], c[mt][nt][2], c[mt][nt][3]);
        }
    }
}

// ---------------- inter-chunk recurrence (parallelized over elements) ----------------
__global__ void scan_kernel(const __half* __restrict__ statesh,
                            const float* __restrict__ Acum,
                            __half* __restrict__ prevh)
{
    int seg = blockIdx.x;
    int h = blockIdx.y, b = blockIdx.z;
    int tid = threadIdx.x;
    int e2 = seg * 1024 + tid;
    float2 carry[4];
#pragma unroll
    for (int t = 0; t < 4; ++t) carry[t] = make_float2(0.f, 0.f);
    for (int cc = 0; cc < NCHUNK; ++cc) {
        float cd = expf(Acum[(((size_t)b * NHEADS + h) * NCHUNK + cc) * CSIZE + CSIZE - 1]);
        size_t base2 = ((((size_t)b * NCHUNK + cc) * NHEADS + h) * (HDIM * NSTATE)) >> 1;
#pragma unroll
        for (int t = 0; t < 4; ++t) {
            size_t idx = base2 + e2 + t * 256;
            float2 sf = __half22float2(((const __half2*)statesh)[idx]);
            __half2 pv; pv.x = __float2half(carry[t].x); pv.y = __float2half(carry[t].y);
            ((__half2*)prevh)[idx] = pv;
            carry[t].x = cd * carry[t].x + sf.x;
            carry[t].y = cd * carry[t].y + sf.y;
        }
    }
}

// =====================================================================
// Y via mma: Y[i,p] = M @ X + Ce @ prev^T + D*x  (fp16 output)
// =====================================================================
__global__ void __launch_bounds__(256) y_mma(
    const __half* __restrict__ xBCh, const float* __restrict__ dtv,
    const float* __restrict__ Acum, const __half* __restrict__ CBh,
    const __half* __restrict__ prevh, const float* __restrict__ Dp,
    __half* __restrict__ Yh)
{
    __shared__ float Ac[CSIZE], dts[CSIZE], rowf[CSIZE], eA[CSIZE], colf[64];
    __shared__ __align__(1024) __half Ms[CSIZE * 64];
    __shared__ __align__(1024) __half Xs[64 * 64];
    const uint32_t sM = smem_u32(Ms), sXs = smem_u32(Xs);

    const int cc = blockIdx.x, h = blockIdx.y, b = blockIdx.z;
    const int tid = threadIdx.x, wid = tid >> 5, lane = tid & 31;
    const int wm = (wid & 3) * 64;
    const int wn = (wid >> 2) * 32;
    const int l0 = b * LSEQ + cc * CSIZE;

    Ac[tid]  = Acum[(((size_t)b * NHEADS + h) * NCHUNK + cc) * CSIZE + tid];
    dts[tid] = dtv[((size_t)b * NHEADS + h) * LSEQ + cc * CSIZE + tid];
    __syncthreads();
    eA[tid] = __expf(Ac[tid]);

    const __half* CBb = CBh + ((size_t)b * NCHUNK + cc) * CSIZE * CSIZE;

    float c[4][4][4];
#pragma unroll
    for (int mt = 0; mt < 4; ++mt)
#pragma unroll
        for (int nt = 0; nt < 4; ++nt)
#pragma unroll
            for (int q = 0; q < 4; ++q) c[mt][nt][q] = 0.f;

    for (int jt = 0; jt < CSIZE; jt += 64) {
        float A_ref = Ac[jt + 63];
        if (tid < 64) colf[tid] = __expf(A_ref - Ac[jt + tid]) * dts[jt + tid];
        rowf[tid] = __expf(Ac[tid] - A_ref);
        __syncthreads();
#pragma unroll
        for (int it = 0; it < 8; ++it) {
            int u = tid + it * 256;
            int i = u >> 3, cu = u & 7;
            float v[8];
            if (i < jt) {
#pragma unroll
                for (int e = 0; e < 8; ++e) v[e] = 0.f;
            } else {
                uint4 cbv = *(const uint4*)&CBb[(size_t)i * CSIZE + jt + cu * 8];
                __half2* ch2 = (__half2*)&cbv;
                float cf[8];
#pragma unroll
                for (int e2 = 0; e2 < 4; ++e2) {
                    float2 f = __half22float2(ch2[e2]);
                    cf[e2 * 2] = f.x; cf[e2 * 2 + 1] = f.y;
                }
                if (i >= jt + 64) {
                    float rf = rowf[i];
#pragma unroll
                    for (int e = 0; e < 8; ++e) v[e] = cf[e] * rf * colf[cu * 8 + e];
                } else {
#pragma unroll
                    for (int e = 0; e < 8; ++e) {
                        int j = jt + cu * 8 + e;
                        v[e] = (j <= i) ? cf[e] * __expf(Ac[i] - Ac[j]) * dts[j] : 0.f;
                    }
                }
            }
            *(uint4*)((char*)Ms + SW128((uint32_t)(i * 128 + cu * 16))) = pack8h(v);
        }
#pragma unroll
        for (int it = 0; it < 2; ++it) {
            int u = tid + it * 256;
            int j = u >> 3, cu = u & 7;
            uint4 v = *(const uint4*)&xBCh[(size_t)(l0 + jt + j) * CONVDIM + h * HDIM + cu * 8];
            *(uint4*)((char*)Xs + SW128((uint32_t)(j * 128 + cu * 16))) = v;
        }
        __syncthreads();
#pragma unroll
        for (int ks = 0; ks < 4; ++ks) {
            uint32_t a[4][4], bf[4][2];
#pragma unroll
            for (int mt = 0; mt < 4; ++mt) {
                int row = wm + mt * 16 + (lane & 15);
                int kb  = ks * 32 + (lane >> 4) * 16;
                ldsm4(a[mt][0], a[mt][1], a[mt][2], a[mt][3],
                      sM + SW128((uint32_t)(row * 128 + kb)));
            }
#pragma unroll
            for (int nt2 = 0; nt2 < 2; ++nt2) {
                int row = ks * 16 + ((lane >> 3) & 1) * 8 + (lane & 7);
                int col = wn + nt2 * 16 + (lane >> 4) * 8;
                uint32_t r0, r1, r2, r3;
                ldsm4t(r0, r1, r2, r3, sXs + SW128((uint32_t)(row * 128 + col * 2)));
                bf[nt2 * 2][0] = r0; bf[nt2 * 2][1] = r1;
                bf[nt2 * 2 + 1][0] = r2; bf[nt2 * 2 + 1][1] = r3;
            }
#pragma unroll
            for (int mt = 0; mt < 4; ++mt)
#pragma unroll
                for (int nt = 0; nt < 4; ++nt)
                    mma16816(c[mt][nt], a[mt], bf[nt]);
        }
        __syncthreads();
    }

    const __half* pvb = prevh + (((size_t)b * NCHUNK + cc) * NHEADS + h) * (HDIM * NSTATE);
    for (int nt0 = 0; nt0 < NSTATE; nt0 += 64) {
#pragma unroll
        for (int it = 0; it < 8; ++it) {
            int u = tid + it * 256;
            int i = u >> 3, cu = u & 7;
            uint4 v = *(const uint4*)&xBCh[(size_t)(l0 + i) * CONVDIM + INTERD + NSTATE + nt0 + cu * 8];
            __half2 ea2 = __float2half2_rn(eA[i]);
            *(uint4*)((char*)Ms + SW128((uint32_t)(i * 128 + cu * 16))) = mul8h(v, ea2);
        }
#pragma unroll
        for (int it = 0; it < 2; ++it) {
            int u = tid + it * 256;
            int p = u >> 3, cu = u & 7;
            uint4 v = *(const uint4*)(pvb + (size_t)p * NSTATE + nt0 + cu * 8);
            *(uint4*)((char*)Xs + SW128((uint32_t)(p * 128 + cu * 16))) = v;
        }
        __syncthreads();
#pragma unroll
        for (int ks = 0; ks < 4; ++ks) {
            uint32_t a[4][4], bf[4][2];
#pragma unroll
            for (int mt = 0; mt < 4; ++mt) {
                int row = wm + mt * 16 + (lane & 15);
                int kb  = ks * 32 + (lane >> 4) * 16;
                ldsm4(a[mt][0], a[mt][1], a[mt][2], a[mt][3],
                      sM + SW128((uint32_t)(row * 128 + kb)));
            }
#pragma unroll
            for (int nt2 = 0; nt2 < 2; ++nt2) {
                int prow = wn + nt2 * 16 + ((lane >> 4) & 1) * 8 + (lane & 7);
                int kb   = ks * 32 + ((lane >> 3) & 1) * 16;
                uint32_t r0, r1, r2, r3;
                ldsm4(r0, r1, r2, r3, sXs + SW128((uint32_t)(prow * 128 + kb)));
                bf[nt2 * 2][0] = r0; bf[nt2 * 2][1] = r1;
                bf[nt2 * 2 + 1][0] = r2; bf[nt2 * 2 + 1][1] = r3;
            }
#pragma unroll
            for (int mt = 0; mt < 4; ++mt)
#pragma unroll
                for (int nt = 0; nt < 4; ++nt)
                    mma16816(c[mt][nt], a[mt], bf[nt]);
        }
        __syncthreads();
    }

    float Dh = Dp[h];
#pragma unroll
    for (int mt = 0; mt < 4; ++mt) {
        int i0 = wm + mt * 16 + (lane >> 2);
#pragma unroll
        for (int nt = 0; nt < 4; ++nt) {
            int p = wn + nt * 8 + (lane & 3) * 2;
#pragma unroll
            for (int half = 0; half < 2; ++half) {
                int i = i0 + half * 8;
                __half2 xh = *(const __half2*)&xBCh[(size_t)(l0 + i) * CONVDIM + h * HDIM + p];
                float2 xv = __half22float2(xh);
                store2(&Yh[(size_t)(l0 + i) * INTERD + h * HDIM + p],
                       c[mt][nt][half * 2 + 0] + Dh * xv.x,
                       c[mt][nt][half * 2 + 1] + Dh * xv.y);
            }
        }
    }
}

// ---------------- gate (silu, fp16 in) + RMSNorm -> fp16 Y2 (vectorized) ----------------
__global__ void gate_rms_kernel(const __half* __restrict__ projh,
                                const float* __restrict__ norm_w,
                                const __half* __restrict__ Yh,
                                __half* __restrict__ Y2)
{
    int row = blockIdx.x, tid = threadIdx.x;
    const __half* gr = projh + (size_t)row * PROJDIM;
    const __half* yr = Yh + (size_t)row * INTERD;
    float yv[16];
    float ss = 0.f;
#pragma unroll
    for (int t = 0; t < 2; ++t) {
        int idx4 = tid + t * 256;          // uint4 index (8 halves)
        uint4 gv = *(const uint4*)(gr + idx4 * 8);
        uint4 yvv = *(const uint4*)(yr + idx4 * 8);
        __half2* g2 = (__half2*)&gv;
        __half2* y2 = (__half2*)&yvv;
#pragma unroll
        for (int e2 = 0; e2 < 4; ++e2) {
            float2 gf = __half22float2(g2[e2]);
            float2 yf = __half22float2(y2[e2]);
            float v0 = yf.x * (gf.x / (1.f + __expf(-gf.x)));
            float v1 = yf.y * (gf.y / (1.f + __expf(-gf.y)));
            yv[t * 8 + e2 * 2]     = v0;
            yv[t * 8 + e2 * 2 + 1] = v1;
            ss += v0 * v0 + v1 * v1;
        }
    }
    __shared__ float red[8];
#pragma unroll
    for (int o = 16; o > 0; o >>= 1) ss += __shfl_xor_sync(0xffffffff, ss, o);
    if ((tid & 31) == 0) red[tid >> 5] = ss;
    __syncthreads();
    float tot = 0.f;
#pragma unroll
    for (int w = 0; w < 8; ++w) tot += red[w];
    float scale = rsqrtf(tot / (float)INTERD + EPSV);
    __half* y2r = Y2 + (size_t)row * INTERD;
#pragma unroll
    for (int t = 0; t < 2; ++t) {
        int idx4 = tid + t * 256;
        float4 w0 = *(const float4*)(norm_w + idx4 * 8);
        float4 w1 = *(const float4*)(norm_w + idx4 * 8 + 4);
        float v[8];
        v[0] = yv[t * 8 + 0] * scale * w0.x;
        v[1] = yv[t * 8 + 1] * scale * w0.y;
        v[2] = yv[t * 8 + 2] * scale * w0.z;
        v[3] = yv[t * 8 + 3] * scale * w0.w;
        v[4] = yv[t * 8 + 4] * scale * w1.x;
        v[5] = yv[t * 8 + 5] * scale * w1.y;
        v[6] = yv[t * 8 + 6] * scale * w1.z;
        v[7] = yv[t * 8 + 7] * scale * w1.w;
        *(uint4*)(y2r + idx4 * 8) = pack8h(v);
    }
}

// ---------------- launch (single stream, graph-capture safe) ----------------
extern "C" void kernel_launch(void* const* d_in, const int* in_sizes, int n_in,
                              void* d_out, int out_size)
{
    const float* hs      = (const float*)d_in[0];
    const float* W_in    = (const float*)d_in[1];
    const float* conv_w  = (const float*)d_in[2];
    const float* conv_b  = (const float*)d_in[3];
    const float* dt_bias = (const float*)d_in[4];
    const float* A_log   = (const float*)d_in[5];
    const float* Dp      = (const float*)d_in[6];
    const float* norm_w  = (const float*)d_in[7];
    const float* W_out   = (const float*)d_in[8];
    float* out = (float*)d_out;

    float *dtv, *Acum;
    __half *projh, *xBCh, *CBh, *statesh, *prevh, *Yh, *A2, *Win2, *Y2, *Wout2;
    cudaGetSymbolAddress((void**)&projh,   g_projh);
    cudaGetSymbolAddress((void**)&xBCh,    g_xBCh);
    cudaGetSymbolAddress((void**)&dtv,     g_dtv);
    cudaGetSymbolAddress((void**)&Acum,    g_Acum);
    cudaGetSymbolAddress((void**)&CBh,     g_CBh);
    cudaGetSymbolAddress((void**)&statesh, g_statesh);
    cudaGetSymbolAddress((void**)&prevh,   g_prevh);
    cudaGetSymbolAddress((void**)&Yh,      g_Yh);
    cudaGetSymbolAddress((void**)&A2,      g_A2);
    cudaGetSymbolAddress((void**)&Win2,    g_Win2);
    cudaGetSymbolAddress((void**)&Y2,      g_Y2);
    cudaGetSymbolAddress((void**)&Wout2,   g_Wout2);

    cudaFuncSetAttribute(gemm_fp16_mma<__half>,
                         cudaFuncAttributeMaxDynamicSharedMemorySize, TSMEM);
    cudaFuncSetAttribute(gemm_fp16_mma<float>,
                         cudaFuncAttributeMaxDynamicSharedMemorySize, TSMEM);
    cudaFuncSetAttribute(states_mma,
                         cudaFuncAttributeMaxDynamicSharedMemorySize, SSM_SMEM);
    cudaFuncSetAttribute(cb_mma,
                         cudaFuncAttributeMaxDynamicSharedMemorySize, CB_SMEM);

    // 0) fused fp32 -> fp16 conversion (hs, W_in, W_out)
    {
        long long tot = CVT_T1 + CVT_T2 + CVT_T3;
        cvt_all_kernel<<<(unsigned)((tot + 255) / 256), 256>>>(
            hs, W_in, W_out, A2, Win2, Wout2);
    }

    // 1) proj = hs @ W_in^T  (fp16 output)
    gemm_fp16_mma<__half><<<dim3(BL / 128, (PROJDIM + 127) / 128), 256, TSMEM>>>(
        A2, Win2, projh, BL, PROJDIM, DMODEL, PROJDIM);

    // 2) conv + silu -> fp16 xBC (2ch x 8 timesteps/thread)
    {
        int total = (BL / 8) * (CONVDIM / 2);
        conv_silu_kernel<<<(total + 255) / 256, 256>>>(projh, conv_w, conv_b, xBCh);
    }

    // 3) softplus(dt) + cumsum (warp-shuffle scan, [b][h][l] dtv)
    dt_acum_kernel<<<dim3(NCHUNK, NHEADS, BATCH), CSIZE>>>(projh, dt_bias, A_log, dtv, Acum);

    // 4) CB = C . B^T via fp16 mma -> fp16
    cb_mma<<<dim3(2, 2, BATCH * NCHUNK), 256, CB_SMEM>>>(xBCh, CBh);

    // 5) states via mma -> fp16
    states_mma<<<dim3(NCHUNK, NHEADS, BATCH), 128, SSM_SMEM>>>(xBCh, dtv, Acum, statesh);

    // 6) scan -> fp16 prev (parallelized: 512 CTAs)
    scan_kernel<<<dim3(4, NHEADS, BATCH), 256>>>(statesh, Acum, prevh);

    // 7) Y via mma (Ydiag + Yoff + D*x) -> fp16
    y_mma<<<dim3(NCHUNK, NHEADS, BATCH), 256>>>(xBCh, dtv, Acum, CBh, prevh, Dp, Yh);

    // 8) gate + RMSNorm -> fp16 (vectorized)
    gate_rms_kernel<<<BL, 256>>>(projh, norm_w, Yh, Y2);

    // 9) out = Y @ W_out^T (fp32 output)
    gemm_fp16_mma<float><<<dim3(BL / 128, DMODEL / 128), 256, TSMEM>>>(
        Y2, Wout2, out, BL, DMODEL, INTERD, DMODEL);
}